// round 5
// baseline (speedup 1.0000x reference)
#include <cuda_runtime.h>
#include <cuda_bf16.h>
#include <cstdint>

#define TPB 512
#define MAX_NODES 50000

// ---------------- device scratch ----------------
__device__ float g_agg[MAX_NODES * 128];
__device__ float g_esum[128];
__device__ float g_nsum[128];
__device__ int   g_is64;
// prepped weights: transposed [n][k], bf16 hi/lo, blocked SW128 (128-row tiles). 8 slots.
__device__ __align__(16) unsigned char g_Bh[8 * 49152];
__device__ __align__(16) unsigned char g_Bl[8 * 49152];

// ---------------- helpers ----------------
__device__ __forceinline__ uint32_t s2u(const void* p) {
    uint32_t a;
    asm("{ .reg .u64 t; cvta.to.shared.u64 t, %1; cvt.u32.u64 %0, t; }" : "=r"(a) : "l"(p));
    return a;
}

// blocked SW128 byte offset for bf16 element (row, k) in a tile with ROWS rows.
// atom = 8 rows x 64 bf16 (1024B); atom-col stride = ROWS*128 bytes.
template <int ROWS>
__device__ __forceinline__ uint32_t aoff(int row, int k) {
    uint32_t b = ((uint32_t)(row >> 3) << 10) + (uint32_t)(k >> 6) * (uint32_t)(ROWS * 128)
               + ((uint32_t)(row & 7) << 7) + ((uint32_t)(k & 63) << 1);
    return b ^ ((b >> 3) & 0x70);
}

__device__ __forceinline__ void split2(float v0, float v1, uint32_t& hw, uint32_t& lw) {
    __nv_bfloat16 h0 = __float2bfloat16(v0), h1 = __float2bfloat16(v1);
    __nv_bfloat16 l0 = __float2bfloat16(v0 - __bfloat162float(h0));
    __nv_bfloat16 l1 = __float2bfloat16(v1 - __bfloat162float(h1));
    hw = (uint32_t)__bfloat16_as_ushort(h0) | ((uint32_t)__bfloat16_as_ushort(h1) << 16);
    lw = (uint32_t)__bfloat16_as_ushort(l0) | ((uint32_t)__bfloat16_as_ushort(l1) << 16);
}
__device__ __forceinline__ void store_pair2(char* Ah, char* Al, uint32_t off,
                                            float v0, float v1) {
    uint32_t hw, lw;
    split2(v0, v1, hw, lw);
    *(uint32_t*)(Ah + off) = hw;
    *(uint32_t*)(Al + off) = lw;
}
__device__ __forceinline__ void copy16(char* dst, const unsigned char* src, int bytes) {
    float4* d = (float4*)dst;
    const float4* s = (const float4*)src;
    for (int i = threadIdx.x; i < bytes / 16; i += (int)blockDim.x) d[i] = s[i];
}

// ---------------- mma.sync + ldmatrix ----------------
__device__ __forceinline__ void ldsm_x4(uint32_t* r, uint32_t addr) {
    asm volatile("ldmatrix.sync.aligned.m8n8.x4.shared.b16 {%0,%1,%2,%3}, [%4];"
                 : "=r"(r[0]), "=r"(r[1]), "=r"(r[2]), "=r"(r[3]) : "r"(addr));
}
__device__ __forceinline__ void mma_bf16(float* c, const uint32_t* a, const uint32_t* b) {
    asm volatile(
        "mma.sync.aligned.m16n8k16.row.col.f32.bf16.bf16.f32 "
        "{%0,%1,%2,%3}, {%4,%5,%6,%7}, {%8,%9}, {%0,%1,%2,%3};"
        : "+f"(c[0]), "+f"(c[1]), "+f"(c[2]), "+f"(c[3])
        : "r"(a[0]), "r"(a[1]), "r"(a[2]), "r"(a[3]), "r"(b[0]), "r"(b[1]));
}

// One emulated-fp32 layer: acc = Ah*Bh + Ah*Bl + Al*Bh over K (multiple of 16).
// Warp computes MT*16 rows x 64 cols (8 n-tiles). B loaded 2 n-tiles per ldsm_x4.
template <int AROWS, int MT, int K>
__device__ __forceinline__ void layer_mma(uint32_t ahb, uint32_t alb,
                                          uint32_t whb, uint32_t wlb,
                                          int mrow0, int ncol0,
                                          float acc[MT * 8][4]) {
    const int lane = threadIdx.x & 31;
    const int aRow = lane & 15;
    const int aKc  = (lane >> 4) * 8;
    const int bRow = (lane & 7) + ((lane >> 4) & 1) * 8;
    const int bKc  = ((lane >> 3) & 1) * 8;
#pragma unroll
    for (int i = 0; i < MT * 8; i++) {
        acc[i][0] = 0.f; acc[i][1] = 0.f; acc[i][2] = 0.f; acc[i][3] = 0.f;
    }
#pragma unroll
    for (int ks = 0; ks < K / 16; ks++) {
        const int k0 = ks * 16;
        uint32_t ah[MT][4], al[MT][4];
#pragma unroll
        for (int mt = 0; mt < MT; mt++) {
            uint32_t off = aoff<AROWS>(mrow0 + mt * 16 + aRow, k0 + aKc);
            ldsm_x4(ah[mt], ahb + off);
            ldsm_x4(al[mt], alb + off);
        }
#pragma unroll
        for (int np = 0; np < 4; np++) {
            // one x4 covers n-tiles (2*np, 2*np+1): regs [0,1] and [2,3]
            uint32_t off = aoff<128>(ncol0 + np * 16 + bRow, k0 + bKc);
            uint32_t bh[4], bl[4];
            ldsm_x4(bh, whb + off);
            ldsm_x4(bl, wlb + off);
#pragma unroll
            for (int mt = 0; mt < MT; mt++) {
                float* c0 = acc[mt * 8 + np * 2];
                float* c1 = acc[mt * 8 + np * 2 + 1];
                mma_bf16(c0, ah[mt], bh);
                mma_bf16(c0, ah[mt], bl);
                mma_bf16(c0, al[mt], bh);
                mma_bf16(c1, ah[mt], bh + 2);
                mma_bf16(c1, ah[mt], bl + 2);
                mma_bf16(c1, al[mt], bh + 2);
            }
        }
    }
}

// Epilogue: add bias (+relu, split hi/lo back into A smem) or write fp32 outS (stride 128).
template <int AROWS, int MT, bool LAST>
__device__ __forceinline__ void layer_epi(float acc[MT * 8][4], const float* sBias,
                                          char* Ah, char* Al, float* outS,
                                          int mrow0, int ncol0) {
    const int lane = threadIdx.x & 31;
    const int r0 = lane >> 2, cOff = (lane & 3) * 2;
#pragma unroll
    for (int mt = 0; mt < MT; mt++) {
#pragma unroll
        for (int nt = 0; nt < 8; nt++) {
            const int col = ncol0 + nt * 8 + cOff;
            const float b0 = sBias[col], b1 = sBias[col + 1];
            float* a = acc[mt * 8 + nt];
            const int row = mrow0 + mt * 16 + r0;
            if (LAST) {
                outS[row * 128 + col]           = a[0] + b0;
                outS[row * 128 + col + 1]       = a[1] + b1;
                outS[(row + 8) * 128 + col]     = a[2] + b0;
                outS[(row + 8) * 128 + col + 1] = a[3] + b1;
            } else {
                store_pair2(Ah, Al, aoff<AROWS>(row, col),
                            fmaxf(a[0] + b0, 0.f), fmaxf(a[1] + b1, 0.f));
                store_pair2(Ah, Al, aoff<AROWS>(row + 8, col),
                            fmaxf(a[2] + b0, 0.f), fmaxf(a[3] + b1, 0.f));
            }
        }
    }
}

// ---------------- prep kernels ----------------
__global__ void detect_kernel(const unsigned* __restrict__ p, int E) {
    if (threadIdx.x == 0) g_is64 = 1;
    __syncthreads();
    const int n = E < 2048 ? E : 2048;
    bool nz = false;
    for (int i = threadIdx.x; i < n; i += 256)
        if (p[2 * i + 1] != 0) nz = true;
    if (nz) g_is64 = 0;
}
__global__ void zero_kernel(long long total) {
    long long i = (long long)blockIdx.x * blockDim.x + threadIdx.x;
    const long long stride = (long long)gridDim.x * blockDim.x;
    for (; i < total; i += stride) g_agg[i] = 0.f;
    if (blockIdx.x == 0 && threadIdx.x < 128) {
        g_esum[threadIdx.x] = 0.f;
        g_nsum[threadIdx.x] = 0.f;
    }
}
// transpose w[K][128] -> B[n][k] bf16 hi/lo, blocked SW128 (128-row tiles)
__global__ void prep_kernel(const float* w0, const float* w1, const float* w2, const float* w3,
                            const float* w4, const float* w5, const float* w6, const float* w7) {
    const float* ws[8] = {w0, w1, w2, w3, w4, w5, w6, w7};
    const int KR[8] = {64, 128, 128, 128, 160, 128, 128, 128};
    const int KP[8] = {64, 128, 128, 128, 192, 128, 128, 128};
    const int s = blockIdx.x;
    const float* w = ws[s];
    const int kr = KR[s], kp = KP[s];
    unsigned char* bh = g_Bh + s * 49152;
    unsigned char* bl = g_Bl + s * 49152;
    for (int i = threadIdx.x; i < 128 * kp; i += 256) {
        int n = i & 127, k = i >> 7;
        float v = (k < kr) ? w[k * 128 + n] : 0.f;
        __nv_bfloat16 h = __float2bfloat16(v);
        __nv_bfloat16 l = __float2bfloat16(v - __bfloat162float(h));
        uint32_t o = aoff<128>(n, k);
        *(__nv_bfloat16*)(bh + o) = h;
        *(__nv_bfloat16*)(bl + o) = l;
    }
}

// ---------------- edge kernel: 256-row tiles, 512 threads ----------------
// smem: Ah 0..64K | Al 64K..128K | Wh 128K..160K | Wl 160K..192K
//       sBias @196608(512B) | sSrc @197120(1KB) | sDst @198144(1KB)
// outS (256x128 fp32 = 128KB) overlaps Ah+Al.
#define E_SMEM (199168 + 1024)

__global__ void __launch_bounds__(TPB, 1)
edge_kernel(const float* __restrict__ x, const float* __restrict__ ea,
            const float* __restrict__ u, const void* __restrict__ ei,
            const float* __restrict__ b1, const float* __restrict__ b2,
            const float* __restrict__ b3, const float* __restrict__ b4,
            float* __restrict__ e_out, int N, int E) {
    extern __shared__ __align__(16) char smraw[];
    char* sm = (char*)((((uintptr_t)smraw) + 1023) & ~(uintptr_t)1023);
    char* Ah = sm;
    char* Al = sm + 65536;
    char* Wh = sm + 131072;
    char* Wl = sm + 163840;
    float* outS  = (float*)sm;
    float* sBias = (float*)(sm + 196608);
    int* sSrc = (int*)(sm + 197120);
    int* sDst = (int*)(sm + 198144);
    const uint32_t ahb = s2u(Ah), alb = s2u(Al), whb = s2u(Wh), wlb = s2u(Wl);

    const int tid = threadIdx.x, wid = tid >> 5;
    const int mrow0 = (wid >> 1) * 32, ncol0 = (wid & 1) * 64;
    const long long eBase = (long long)blockIdx.x * 256;
    const int is64 = g_is64;

    for (int i = tid; i < 256; i += TPB) {
        long long e = eBase + i;
        int s = 0, d = 0;
        if (e < E) {
            if (is64) { const long long* q = (const long long*)ei; s = (int)q[e]; d = (int)q[E + e]; }
            else      { const int* q = (const int*)ei;             s = q[e];      d = q[E + e]; }
        }
        sSrc[i] = s; sDst[i] = d;
    }
    __syncthreads();

    // stage layer-1 A: concat(ea, x[src], x[dst], u), K=64, 256 rows
    for (int i = tid; i < 256 * 32; i += TPB) {
        int row = i & 255, k = (i >> 8) * 2;
        long long e = eBase + row;
        float v0 = 0.f, v1 = 0.f;
        if (e < E) {
            if (k < 16)      { v0 = ea[e * 16 + k];            v1 = ea[e * 16 + k + 1]; }
            else if (k < 32) { long long s = sSrc[row]; v0 = x[s * 16 + k - 16]; v1 = x[s * 16 + k - 15]; }
            else if (k < 48) { long long d = sDst[row]; v0 = x[d * 16 + k - 32]; v1 = x[d * 16 + k - 31]; }
            else             { v0 = u[k - 48];                 v1 = u[k - 47]; }
        }
        store_pair2(Ah, Al, aoff<256>(row, k), v0, v1);
    }

    const float* bs[4] = {b1, b2, b3, b4};
    const int wsz[4] = {16384, 32768, 32768, 32768};

    float acc[16][4];
#pragma unroll 1
    for (int l = 0; l < 4; l++) {
        copy16(Wh, g_Bh + l * 49152, wsz[l]);
        copy16(Wl, g_Bl + l * 49152, wsz[l]);
        if (tid < 128) sBias[tid] = bs[l][tid];
        __syncthreads();
        if (l == 0) layer_mma<256, 2, 64>(ahb, alb, whb, wlb, mrow0, ncol0, acc);
        else        layer_mma<256, 2, 128>(ahb, alb, whb, wlb, mrow0, ncol0, acc);
        __syncthreads();
        if (l < 3) layer_epi<256, 2, false>(acc, sBias, Ah, Al, nullptr, mrow0, ncol0);
        else       layer_epi<256, 2, true>(acc, sBias, nullptr, nullptr, outS, mrow0, ncol0);
    }
    __syncthreads();

    // final: coalesced e_out stores + segment-sum atomics
    for (int i = tid; i < 256 * 32; i += TPB) {
        int row = i >> 5, q = i & 31;
        long long e = eBase + row;
        if (e < E) {
            float4 v = *(float4*)(outS + row * 128 + q * 4);
            *(float4*)(e_out + e * 128 + q * 4) = v;
            float* ap = g_agg + (long long)sDst[row] * 128 + q * 4;
            atomicAdd(ap + 0, v.x); atomicAdd(ap + 1, v.y);
            atomicAdd(ap + 2, v.z); atomicAdd(ap + 3, v.w);
        }
    }
}

// ---------------- node kernel: 128-row tiles, 512 threads ----------------
// smem: Ah 0..48K | Al 48K..96K | Wh 96K..144K | Wl 144K..192K | sBias @196608
// outS (128x128 fp32 = 64KB) overlaps Ah.
#define N_SMEM (197120 + 1024)

__global__ void __launch_bounds__(TPB, 1)
node_kernel(const float* __restrict__ x, const float* __restrict__ u,
            const float* __restrict__ b1, const float* __restrict__ b2,
            const float* __restrict__ b3, const float* __restrict__ b4,
            float* __restrict__ n_out, int N) {
    extern __shared__ __align__(16) char smraw[];
    char* sm = (char*)((((uintptr_t)smraw) + 1023) & ~(uintptr_t)1023);
    char* Ah = sm;
    char* Al = sm + 49152;
    char* Wh = sm + 98304;
    char* Wl = sm + 147456;
    float* outS  = (float*)sm;
    float* sBias = (float*)(sm + 196608);
    const uint32_t ahb = s2u(Ah), alb = s2u(Al), whb = s2u(Wh), wlb = s2u(Wl);

    const int tid = threadIdx.x, wid = tid >> 5;
    const int mrow0 = (wid >> 1) * 16, ncol0 = (wid & 1) * 64;
    const long long nBase = (long long)blockIdx.x * 128;
    const int lim = (int)(((N - nBase) < 128) ? (N - nBase) : 128);

    // esum contribution: column sums of g_agg rows owned by this block
    {
        int col = tid & 127, quarter = tid >> 7;
        float s = 0.f;
        for (int r = quarter * 32; r < quarter * 32 + 32 && r < lim; r++)
            s += g_agg[(nBase + r) * 128 + col];
        atomicAdd(&g_esum[col], s);
    }

    // stage layer-1 A: concat(x, agg, u) padded to K=192
    for (int i = tid; i < 128 * 96; i += TPB) {
        int row = i & 127, k = (i >> 7) * 2;
        long long n = nBase + row;
        float v0 = 0.f, v1 = 0.f;
        if (n < N) {
            if (k < 16)       { v0 = x[n * 16 + k];            v1 = x[n * 16 + k + 1]; }
            else if (k < 144) { v0 = g_agg[n * 128 + k - 16];  v1 = g_agg[n * 128 + k - 15]; }
            else if (k < 160) { v0 = u[k - 144];               v1 = u[k - 143]; }
        }
        store_pair2(Ah, Al, aoff<128>(row, k), v0, v1);
    }

    const float* bs[4] = {b1, b2, b3, b4};
    const int wsz[4] = {49152, 32768, 32768, 32768};

    float acc[8][4];
#pragma unroll 1
    for (int l = 0; l < 4; l++) {
        copy16(Wh, g_Bh + (4 + l) * 49152, wsz[l]);
        copy16(Wl, g_Bl + (4 + l) * 49152, wsz[l]);
        if (tid < 128) sBias[tid] = bs[l][tid];
        __syncthreads();
        if (l == 0) layer_mma<128, 1, 192>(ahb, alb, whb, wlb, mrow0, ncol0, acc);
        else        layer_mma<128, 1, 128>(ahb, alb, whb, wlb, mrow0, ncol0, acc);
        __syncthreads();
        if (l < 3) layer_epi<128, 1, false>(acc, sBias, Ah, Al, nullptr, mrow0, ncol0);
        else       layer_epi<128, 1, true>(acc, sBias, nullptr, nullptr, outS, mrow0, ncol0);
    }
    __syncthreads();

    for (int i = tid; i < 128 * 32; i += TPB) {
        int row = i >> 5, q = i & 31;
        long long n = nBase + row;
        if (n < N)
            *(float4*)(n_out + n * 128 + q * 4) = *(float4*)(outS + row * 128 + q * 4);
    }
    __syncthreads();
    {
        int col = tid & 127, quarter = tid >> 7;
        float s = 0.f;
        for (int r = quarter * 32; r < quarter * 32 + 32 && r < lim; r++)
            s += outS[r * 128 + col];
        atomicAdd(&g_nsum[col], s);
    }
}

// ---------------- global kernel ----------------
__global__ void global_kernel(const float* __restrict__ u,
                              const float* __restrict__ w1, const float* __restrict__ b1,
                              const float* __restrict__ w2, const float* __restrict__ b2,
                              const float* __restrict__ w3, const float* __restrict__ b3,
                              const float* __restrict__ w4, const float* __restrict__ b4,
                              float* __restrict__ g_out) {
    __shared__ float sIn[272];
    __shared__ float sH[128];
    const int t = threadIdx.x;  // 128 threads
    if (t < 16) sIn[t] = u[t];
    sIn[16 + t]  = g_nsum[t];
    sIn[144 + t] = g_esum[t];
    __syncthreads();

    float a = b1[t];
#pragma unroll 4
    for (int k = 0; k < 272; k++) a = fmaf(sIn[k], w1[k * 128 + t], a);
    a = fmaxf(a, 0.f);
    __syncthreads(); sH[t] = a; __syncthreads();

    a = b2[t];
#pragma unroll 4
    for (int k = 0; k < 128; k++) a = fmaf(sH[k], w2[k * 128 + t], a);
    a = fmaxf(a, 0.f);
    __syncthreads(); sH[t] = a; __syncthreads();

    a = b3[t];
#pragma unroll 4
    for (int k = 0; k < 128; k++) a = fmaf(sH[k], w3[k * 128 + t], a);
    a = fmaxf(a, 0.f);
    __syncthreads(); sH[t] = a; __syncthreads();

    a = b4[t];
#pragma unroll 4
    for (int k = 0; k < 128; k++) a = fmaf(sH[k], w4[k * 128 + t], a);
    g_out[t] = a;
}

// ---------------- host launcher ----------------
extern "C" void kernel_launch(void* const* d_in, const int* in_sizes, int n_in,
                              void* d_out, int out_size) {
    const float* x  = (const float*)d_in[0];
    const float* ea = (const float*)d_in[1];
    const float* u  = (const float*)d_in[2];
    const void*  ei = d_in[3];

    const int N = in_sizes[0] / 16;
    const int E = in_sizes[1] / 16;

    float* out   = (float*)d_out;
    float* e_out = out;
    float* n_out = out + (long long)E * 128;
    float* g_out = out + (long long)E * 128 + (long long)N * 128;

    cudaFuncSetAttribute(edge_kernel, cudaFuncAttributeMaxDynamicSharedMemorySize, E_SMEM);
    cudaFuncSetAttribute(node_kernel, cudaFuncAttributeMaxDynamicSharedMemorySize, N_SMEM);

    detect_kernel<<<1, 256>>>((const unsigned*)ei, E);
    zero_kernel<<<1024, 256>>>((long long)N * 128);
    prep_kernel<<<8, 256>>>((const float*)d_in[4],  (const float*)d_in[6],
                            (const float*)d_in[8],  (const float*)d_in[10],
                            (const float*)d_in[12], (const float*)d_in[14],
                            (const float*)d_in[16], (const float*)d_in[18]);
    edge_kernel<<<(E + 255) / 256, TPB, E_SMEM>>>(
        x, ea, u, ei,
        (const float*)d_in[5], (const float*)d_in[7],
        (const float*)d_in[9], (const float*)d_in[11],
        e_out, N, E);
    node_kernel<<<(N + 127) / 128, TPB, N_SMEM>>>(
        x, u,
        (const float*)d_in[13], (const float*)d_in[15],
        (const float*)d_in[17], (const float*)d_in[19],
        n_out, N);
    global_kernel<<<1, 128>>>(
        u,
        (const float*)d_in[20], (const float*)d_in[21],
        (const float*)d_in[22], (const float*)d_in[23],
        (const float*)d_in[24], (const float*)d_in[25],
        (const float*)d_in[26], (const float*)d_in[27],
        g_out);
}

// round 6
// speedup vs baseline: 1.0451x; 1.0451x over previous
#include <cuda_runtime.h>
#include <cuda_bf16.h>
#include <cstdint>

#define TPB 512
#define MAX_NODES 50000

// ---------------- device scratch ----------------
__device__ float g_agg[MAX_NODES * 128];
__device__ float g_esum[128];
__device__ float g_nsum[128];
__device__ int   g_is64;
// prepped weights: transposed [n][k], bf16 hi/lo, blocked SW128 (128-row tiles). 8 slots.
__device__ __align__(16) unsigned char g_Bh[8 * 49152];
__device__ __align__(16) unsigned char g_Bl[8 * 49152];

// ---------------- helpers ----------------
__device__ __forceinline__ uint32_t s2u(const void* p) {
    uint32_t a;
    asm("{ .reg .u64 t; cvta.to.shared.u64 t, %1; cvt.u32.u64 %0, t; }" : "=r"(a) : "l"(p));
    return a;
}

// blocked SW128 byte offset for bf16 element (row, k) in a tile with ROWS rows.
// atom = 8 rows x 64 bf16 (1024B); atom-col stride = ROWS*128 bytes.
template <int ROWS>
__device__ __forceinline__ uint32_t aoff(int row, int k) {
    uint32_t b = ((uint32_t)(row >> 3) << 10) + (uint32_t)(k >> 6) * (uint32_t)(ROWS * 128)
               + ((uint32_t)(row & 7) << 7) + ((uint32_t)(k & 63) << 1);
    return b ^ ((b >> 3) & 0x70);
}

__device__ __forceinline__ void split2(float v0, float v1, uint32_t& hw, uint32_t& lw) {
    __nv_bfloat16 h0 = __float2bfloat16(v0), h1 = __float2bfloat16(v1);
    __nv_bfloat16 l0 = __float2bfloat16(v0 - __bfloat162float(h0));
    __nv_bfloat16 l1 = __float2bfloat16(v1 - __bfloat162float(h1));
    hw = (uint32_t)__bfloat16_as_ushort(h0) | ((uint32_t)__bfloat16_as_ushort(h1) << 16);
    lw = (uint32_t)__bfloat16_as_ushort(l0) | ((uint32_t)__bfloat16_as_ushort(l1) << 16);
}
__device__ __forceinline__ void store_pair2(char* Ah, char* Al, uint32_t off,
                                            float v0, float v1) {
    uint32_t hw, lw;
    split2(v0, v1, hw, lw);
    *(uint32_t*)(Ah + off) = hw;
    *(uint32_t*)(Al + off) = lw;
}
__device__ __forceinline__ void copy16(char* dst, const unsigned char* src, int bytes) {
    float4* d = (float4*)dst;
    const float4* s = (const float4*)src;
    for (int i = threadIdx.x; i < bytes / 16; i += (int)blockDim.x) d[i] = s[i];
}

// ---------------- mma.sync + ldmatrix ----------------
__device__ __forceinline__ void ldsm_x4(uint32_t* r, uint32_t addr) {
    asm volatile("ldmatrix.sync.aligned.m8n8.x4.shared.b16 {%0,%1,%2,%3}, [%4];"
                 : "=r"(r[0]), "=r"(r[1]), "=r"(r[2]), "=r"(r[3]) : "r"(addr));
}
__device__ __forceinline__ void mma_bf16(float* c, const uint32_t* a, const uint32_t* b) {
    asm volatile(
        "mma.sync.aligned.m16n8k16.row.col.f32.bf16.bf16.f32 "
        "{%0,%1,%2,%3}, {%4,%5,%6,%7}, {%8,%9}, {%0,%1,%2,%3};"
        : "+f"(c[0]), "+f"(c[1]), "+f"(c[2]), "+f"(c[3])
        : "r"(a[0]), "r"(a[1]), "r"(a[2]), "r"(a[3]), "r"(b[0]), "r"(b[1]));
}

// One emulated-fp32 layer: acc = Ah*Bh + Ah*Bl + Al*Bh over K (multiple of 16).
// Warp computes MT*16 rows x NT*8 cols. B loaded 2 n-tiles per ldsm_x4.
// MMAs are issued product-major so each accumulator's reuse distance is 2*MT.
template <int AROWS, int MT, int NT, int K>
__device__ __forceinline__ void layer_mma(uint32_t ahb, uint32_t alb,
                                          uint32_t whb, uint32_t wlb,
                                          int mrow0, int ncol0,
                                          float acc[MT * NT][4]) {
    const int lane = threadIdx.x & 31;
    const int aRow = lane & 15;
    const int aKc  = (lane >> 4) * 8;
    const int bRow = (lane & 7) + ((lane >> 4) & 1) * 8;
    const int bKc  = ((lane >> 3) & 1) * 8;
#pragma unroll
    for (int i = 0; i < MT * NT; i++) {
        acc[i][0] = 0.f; acc[i][1] = 0.f; acc[i][2] = 0.f; acc[i][3] = 0.f;
    }
#pragma unroll 1
    for (int ks = 0; ks < K / 16; ks++) {
        const int k0 = ks * 16;
        uint32_t ah[MT][4], al[MT][4];
#pragma unroll
        for (int mt = 0; mt < MT; mt++) {
            uint32_t off = aoff<AROWS>(mrow0 + mt * 16 + aRow, k0 + aKc);
            ldsm_x4(ah[mt], ahb + off);
            ldsm_x4(al[mt], alb + off);
        }
#pragma unroll
        for (int np = 0; np < NT / 2; np++) {
            // one x4 covers n-tiles (2*np, 2*np+1): regs [0,1] and [2,3]
            uint32_t off = aoff<128>(ncol0 + np * 16 + bRow, k0 + bKc);
            uint32_t bh[4], bl[4];
            ldsm_x4(bh, whb + off);
            ldsm_x4(bl, wlb + off);
            // product-major: accumulator reuse distance = 2*MT
#pragma unroll
            for (int mt = 0; mt < MT; mt++) {
                mma_bf16(acc[mt * NT + np * 2],     ah[mt], bh);
                mma_bf16(acc[mt * NT + np * 2 + 1], ah[mt], bh + 2);
            }
#pragma unroll
            for (int mt = 0; mt < MT; mt++) {
                mma_bf16(acc[mt * NT + np * 2],     ah[mt], bl);
                mma_bf16(acc[mt * NT + np * 2 + 1], ah[mt], bl + 2);
            }
#pragma unroll
            for (int mt = 0; mt < MT; mt++) {
                mma_bf16(acc[mt * NT + np * 2],     al[mt], bh);
                mma_bf16(acc[mt * NT + np * 2 + 1], al[mt], bh + 2);
            }
        }
    }
}

// Epilogue: add bias (+relu, split hi/lo back into A smem) or write fp32 outS (stride 132).
template <int AROWS, int MT, int NT, bool LAST>
__device__ __forceinline__ void layer_epi(float acc[MT * NT][4], const float* sBias,
                                          char* Ah, char* Al, float* outS,
                                          int mrow0, int ncol0) {
    const int lane = threadIdx.x & 31;
    const int r0 = lane >> 2, cOff = (lane & 3) * 2;
#pragma unroll
    for (int mt = 0; mt < MT; mt++) {
#pragma unroll
        for (int nt = 0; nt < NT; nt++) {
            const int col = ncol0 + nt * 8 + cOff;
            const float b0 = sBias[col], b1 = sBias[col + 1];
            float* a = acc[mt * NT + nt];
            const int row = mrow0 + mt * 16 + r0;
            if (LAST) {
                outS[row * 132 + col]           = a[0] + b0;
                outS[row * 132 + col + 1]       = a[1] + b1;
                outS[(row + 8) * 132 + col]     = a[2] + b0;
                outS[(row + 8) * 132 + col + 1] = a[3] + b1;
            } else {
                store_pair2(Ah, Al, aoff<AROWS>(row, col),
                            fmaxf(a[0] + b0, 0.f), fmaxf(a[1] + b1, 0.f));
                store_pair2(Ah, Al, aoff<AROWS>(row + 8, col),
                            fmaxf(a[2] + b0, 0.f), fmaxf(a[3] + b1, 0.f));
            }
        }
    }
}

// ---------------- prep kernels ----------------
__global__ void detect_kernel(const unsigned* __restrict__ p, int E) {
    if (threadIdx.x == 0) g_is64 = 1;
    __syncthreads();
    const int n = E < 2048 ? E : 2048;
    bool nz = false;
    for (int i = threadIdx.x; i < n; i += 256)
        if (p[2 * i + 1] != 0) nz = true;
    if (nz) g_is64 = 0;
}
__global__ void zero_kernel(long long total) {
    long long i = (long long)blockIdx.x * blockDim.x + threadIdx.x;
    const long long stride = (long long)gridDim.x * blockDim.x;
    for (; i < total; i += stride) g_agg[i] = 0.f;
    if (blockIdx.x == 0 && threadIdx.x < 128) {
        g_esum[threadIdx.x] = 0.f;
        g_nsum[threadIdx.x] = 0.f;
    }
}
// transpose w[K][128] -> B[n][k] bf16 hi/lo, blocked SW128 (128-row tiles)
__global__ void prep_kernel(const float* w0, const float* w1, const float* w2, const float* w3,
                            const float* w4, const float* w5, const float* w6, const float* w7) {
    const float* ws[8] = {w0, w1, w2, w3, w4, w5, w6, w7};
    const int KR[8] = {64, 128, 128, 128, 160, 128, 128, 128};
    const int KP[8] = {64, 128, 128, 128, 192, 128, 128, 128};
    const int s = blockIdx.x;
    const float* w = ws[s];
    const int kr = KR[s], kp = KP[s];
    unsigned char* bh = g_Bh + s * 49152;
    unsigned char* bl = g_Bl + s * 49152;
    for (int i = threadIdx.x; i < 128 * kp; i += 256) {
        int n = i & 127, k = i >> 7;
        float v = (k < kr) ? w[k * 128 + n] : 0.f;
        __nv_bfloat16 h = __float2bfloat16(v);
        __nv_bfloat16 l = __float2bfloat16(v - __bfloat162float(h));
        uint32_t o = aoff<128>(n, k);
        *(__nv_bfloat16*)(bh + o) = h;
        *(__nv_bfloat16*)(bl + o) = l;
    }
}

// ---------------- edge kernel: 256-row tiles, 512 threads ----------------
// smem: Ah 0..64K | Al 64K..128K | Wh 128K..160K | Wl 160K..192K
//       sBias0 @196608(512B) | sBias1 @197120 | sSrc @197632(1KB) | sDst @198656(1KB)
// outS (256x132 fp32 = 135168B) overlaps Ah+Al+start of Wh (W dead by then).
#define E_SMEM (199680 + 1024)

__global__ void __launch_bounds__(TPB, 1)
edge_kernel(const float* __restrict__ x, const float* __restrict__ ea,
            const float* __restrict__ u, const void* __restrict__ ei,
            const float* __restrict__ b1, const float* __restrict__ b2,
            const float* __restrict__ b3, const float* __restrict__ b4,
            float* __restrict__ e_out, int N, int E) {
    extern __shared__ __align__(16) char smraw[];
    char* sm = (char*)((((uintptr_t)smraw) + 1023) & ~(uintptr_t)1023);
    char* Ah = sm;
    char* Al = sm + 65536;
    char* Wh = sm + 131072;
    char* Wl = sm + 163840;
    float* outS   = (float*)sm;
    float* sBias0 = (float*)(sm + 196608);
    float* sBias1 = (float*)(sm + 197120);
    int* sSrc = (int*)(sm + 197632);
    int* sDst = (int*)(sm + 198656);
    const uint32_t ahb = s2u(Ah), alb = s2u(Al), whb = s2u(Wh), wlb = s2u(Wl);

    const int tid = threadIdx.x, wid = tid >> 5;
    const int mrow0 = (wid >> 1) * 32, ncol0 = (wid & 1) * 64;
    const long long eBase = (long long)blockIdx.x * 256;
    const int is64 = g_is64;

    for (int i = tid; i < 256; i += TPB) {
        long long e = eBase + i;
        int s = 0, d = 0;
        if (e < E) {
            if (is64) { const long long* q = (const long long*)ei; s = (int)q[e]; d = (int)q[E + e]; }
            else      { const int* q = (const int*)ei;             s = q[e];      d = q[E + e]; }
        }
        sSrc[i] = s; sDst[i] = d;
    }
    __syncthreads();

    // stage layer-1 A: concat(ea, x[src], x[dst], u), K=64, 256 rows
    for (int i = tid; i < 256 * 32; i += TPB) {
        int row = i & 255, k = (i >> 8) * 2;
        long long e = eBase + row;
        float v0 = 0.f, v1 = 0.f;
        if (e < E) {
            if (k < 16)      { v0 = ea[e * 16 + k];            v1 = ea[e * 16 + k + 1]; }
            else if (k < 32) { long long s = sSrc[row]; v0 = x[s * 16 + k - 16]; v1 = x[s * 16 + k - 15]; }
            else if (k < 48) { long long d = sDst[row]; v0 = x[d * 16 + k - 32]; v1 = x[d * 16 + k - 31]; }
            else             { v0 = u[k - 48];                 v1 = u[k - 47]; }
        }
        store_pair2(Ah, Al, aoff<256>(row, k), v0, v1);
    }
    copy16(Wh, g_Bh, 16384);
    copy16(Wl, g_Bl, 16384);
    if (tid < 128) sBias0[tid] = b1[tid];

    const float* bs[4] = {b1, b2, b3, b4};
    const int wsz[4] = {16384, 32768, 32768, 32768};

    float acc[16][4];
#pragma unroll 1
    for (int l = 0; l < 4; l++) {
        __syncthreads();   // W_l, A_l, bias_l visible
        if (l == 0) layer_mma<256, 2, 8, 64>(ahb, alb, whb, wlb, mrow0, ncol0, acc);
        else        layer_mma<256, 2, 8, 128>(ahb, alb, whb, wlb, mrow0, ncol0, acc);
        __syncthreads();   // all reads of A_l / W_l complete
        float* sb = (l & 1) ? sBias1 : sBias0;
        if (l < 3) {
            layer_epi<256, 2, 8, false>(acc, sb, Ah, Al, nullptr, mrow0, ncol0);
            copy16(Wh, g_Bh + (l + 1) * 49152, wsz[l + 1]);
            copy16(Wl, g_Bl + (l + 1) * 49152, wsz[l + 1]);
            float* nb = (l & 1) ? sBias0 : sBias1;
            if (tid < 128) nb[tid] = bs[l + 1][tid];
        } else {
            layer_epi<256, 2, 8, true>(acc, sb, nullptr, nullptr, outS, mrow0, ncol0);
        }
    }
    __syncthreads();

    // final: coalesced e_out stores + segment-sum atomics
    for (int i = tid; i < 256 * 32; i += TPB) {
        int row = i >> 5, q = i & 31;
        long long e = eBase + row;
        if (e < E) {
            float4 v = *(float4*)(outS + row * 132 + q * 4);
            *(float4*)(e_out + e * 128 + q * 4) = v;
            float* ap = g_agg + (long long)sDst[row] * 128 + q * 4;
            atomicAdd(ap + 0, v.x); atomicAdd(ap + 1, v.y);
            atomicAdd(ap + 2, v.z); atomicAdd(ap + 3, v.w);
        }
    }
}

// ---------------- node kernel: 128-row tiles, 512 threads ----------------
// smem: Ah 0..48K | Al 48K..96K | Wh 96K..144K | Wl 144K..192K
//       sBias0 @196608 | sBias1 @197120
// outS (128x132 fp32 = 67584B) overlaps Ah+Al.
#define N_SMEM (197632 + 1024)

__global__ void __launch_bounds__(TPB, 1)
node_kernel(const float* __restrict__ x, const float* __restrict__ u,
            const float* __restrict__ b1, const float* __restrict__ b2,
            const float* __restrict__ b3, const float* __restrict__ b4,
            float* __restrict__ n_out, int N) {
    extern __shared__ __align__(16) char smraw[];
    char* sm = (char*)((((uintptr_t)smraw) + 1023) & ~(uintptr_t)1023);
    char* Ah = sm;
    char* Al = sm + 49152;
    char* Wh = sm + 98304;
    char* Wl = sm + 147456;
    float* outS   = (float*)sm;
    float* sBias0 = (float*)(sm + 196608);
    float* sBias1 = (float*)(sm + 197120);
    const uint32_t ahb = s2u(Ah), alb = s2u(Al), whb = s2u(Wh), wlb = s2u(Wl);

    const int tid = threadIdx.x, wid = tid >> 5;
    // MT=2/NT=4: warp owns 32 rows x 32 cols
    const int mrow0 = (wid >> 2) * 32, ncol0 = (wid & 3) * 32;
    const long long nBase = (long long)blockIdx.x * 128;
    const int lim = (int)(((N - nBase) < 128) ? (N - nBase) : 128);

    // esum contribution: column sums of g_agg rows owned by this block
    {
        int col = tid & 127, quarter = tid >> 7;
        float s = 0.f;
        for (int r = quarter * 32; r < quarter * 32 + 32 && r < lim; r++)
            s += g_agg[(nBase + r) * 128 + col];
        atomicAdd(&g_esum[col], s);
    }

    // stage layer-1 A: concat(x, agg, u) padded to K=192
    for (int i = tid; i < 128 * 96; i += TPB) {
        int row = i & 127, k = (i >> 7) * 2;
        long long n = nBase + row;
        float v0 = 0.f, v1 = 0.f;
        if (n < N) {
            if (k < 16)       { v0 = x[n * 16 + k];            v1 = x[n * 16 + k + 1]; }
            else if (k < 144) { v0 = g_agg[n * 128 + k - 16];  v1 = g_agg[n * 128 + k - 15]; }
            else if (k < 160) { v0 = u[k - 144];               v1 = u[k - 143]; }
        }
        store_pair2(Ah, Al, aoff<128>(row, k), v0, v1);
    }
    copy16(Wh, g_Bh + 4 * 49152, 49152);
    copy16(Wl, g_Bl + 4 * 49152, 49152);
    if (tid < 128) sBias0[tid] = b1[tid];

    const float* bs[4] = {b1, b2, b3, b4};
    const int wsz[4] = {49152, 32768, 32768, 32768};

    float acc[8][4];
#pragma unroll 1
    for (int l = 0; l < 4; l++) {
        __syncthreads();
        if (l == 0) layer_mma<128, 2, 4, 192>(ahb, alb, whb, wlb, mrow0, ncol0, acc);
        else        layer_mma<128, 2, 4, 128>(ahb, alb, whb, wlb, mrow0, ncol0, acc);
        __syncthreads();
        float* sb = (l & 1) ? sBias1 : sBias0;
        if (l < 3) {
            layer_epi<128, 2, 4, false>(acc, sb, Ah, Al, nullptr, mrow0, ncol0);
            copy16(Wh, g_Bh + (5 + l) * 49152, wsz[l + 1]);
            copy16(Wl, g_Bl + (5 + l) * 49152, wsz[l + 1]);
            float* nb = (l & 1) ? sBias0 : sBias1;
            if (tid < 128) nb[tid] = bs[l + 1][tid];
        } else {
            layer_epi<128, 2, 4, true>(acc, sb, nullptr, nullptr, outS, mrow0, ncol0);
        }
    }
    __syncthreads();

    for (int i = tid; i < 128 * 32; i += TPB) {
        int row = i >> 5, q = i & 31;
        long long n = nBase + row;
        if (n < N)
            *(float4*)(n_out + n * 128 + q * 4) = *(float4*)(outS + row * 132 + q * 4);
    }
    __syncthreads();
    {
        int col = tid & 127, quarter = tid >> 7;
        float s = 0.f;
        for (int r = quarter * 32; r < quarter * 32 + 32 && r < lim; r++)
            s += outS[r * 132 + col];
        atomicAdd(&g_nsum[col], s);
    }
}

// ---------------- global kernel ----------------
__global__ void global_kernel(const float* __restrict__ u,
                              const float* __restrict__ w1, const float* __restrict__ b1,
                              const float* __restrict__ w2, const float* __restrict__ b2,
                              const float* __restrict__ w3, const float* __restrict__ b3,
                              const float* __restrict__ w4, const float* __restrict__ b4,
                              float* __restrict__ g_out) {
    __shared__ float sIn[272];
    __shared__ float sH[128];
    const int t = threadIdx.x;  // 128 threads
    if (t < 16) sIn[t] = u[t];
    sIn[16 + t]  = g_nsum[t];
    sIn[144 + t] = g_esum[t];
    __syncthreads();

    float a = b1[t];
#pragma unroll 4
    for (int k = 0; k < 272; k++) a = fmaf(sIn[k], w1[k * 128 + t], a);
    a = fmaxf(a, 0.f);
    __syncthreads(); sH[t] = a; __syncthreads();

    a = b2[t];
#pragma unroll 4
    for (int k = 0; k < 128; k++) a = fmaf(sH[k], w2[k * 128 + t], a);
    a = fmaxf(a, 0.f);
    __syncthreads(); sH[t] = a; __syncthreads();

    a = b3[t];
#pragma unroll 4
    for (int k = 0; k < 128; k++) a = fmaf(sH[k], w3[k * 128 + t], a);
    a = fmaxf(a, 0.f);
    __syncthreads(); sH[t] = a; __syncthreads();

    a = b4[t];
#pragma unroll 4
    for (int k = 0; k < 128; k++) a = fmaf(sH[k], w4[k * 128 + t], a);
    g_out[t] = a;
}

// ---------------- host launcher ----------------
extern "C" void kernel_launch(void* const* d_in, const int* in_sizes, int n_in,
                              void* d_out, int out_size) {
    const float* x  = (const float*)d_in[0];
    const float* ea = (const float*)d_in[1];
    const float* u  = (const float*)d_in[2];
    const void*  ei = d_in[3];

    const int N = in_sizes[0] / 16;
    const int E = in_sizes[1] / 16;

    float* out   = (float*)d_out;
    float* e_out = out;
    float* n_out = out + (long long)E * 128;
    float* g_out = out + (long long)E * 128 + (long long)N * 128;

    cudaFuncSetAttribute(edge_kernel, cudaFuncAttributeMaxDynamicSharedMemorySize, E_SMEM);
    cudaFuncSetAttribute(node_kernel, cudaFuncAttributeMaxDynamicSharedMemorySize, N_SMEM);

    detect_kernel<<<1, 256>>>((const unsigned*)ei, E);
    zero_kernel<<<1024, 256>>>((long long)N * 128);
    prep_kernel<<<8, 256>>>((const float*)d_in[4],  (const float*)d_in[6],
                            (const float*)d_in[8],  (const float*)d_in[10],
                            (const float*)d_in[12], (const float*)d_in[14],
                            (const float*)d_in[16], (const float*)d_in[18]);
    edge_kernel<<<(E + 255) / 256, TPB, E_SMEM>>>(
        x, ea, u, ei,
        (const float*)d_in[5], (const float*)d_in[7],
        (const float*)d_in[9], (const float*)d_in[11],
        e_out, N, E);
    node_kernel<<<(N + 127) / 128, TPB, N_SMEM>>>(
        x, u,
        (const float*)d_in[13], (const float*)d_in[15],
        (const float*)d_in[17], (const float*)d_in[19],
        n_out, N);
    global_kernel<<<1, 128>>>(
        u,
        (const float*)d_in[20], (const float*)d_in[21],
        (const float*)d_in[22], (const float*)d_in[23],
        (const float*)d_in[24], (const float*)d_in[25],
        (const float*)d_in[26], (const float*)d_in[27],
        g_out);
}

// round 7
// speedup vs baseline: 1.5766x; 1.5086x over previous
#include <cuda_runtime.h>
#include <cuda_bf16.h>
#include <cstdint>

#define MAX_NODES 50000

// ---------------- device scratch ----------------
__device__ float g_agg[MAX_NODES * 128];
__device__ float g_esum[128];
__device__ float g_nsum[128];
__device__ int   g_is64;
// B operands pre-shuffled into mma.sync fragment order.
// [layer][(ks*8+np)*32+lane] -> uint4 {ntile_even b0,b1, ntile_odd b0,b1}
__device__ __align__(16) uint4 g_FH[8][12 * 8 * 32];
__device__ __align__(16) uint4 g_FL[8][12 * 8 * 32];

// ---------------- helpers ----------------
__device__ __forceinline__ uint32_t s2u(const void* p) {
    uint32_t a;
    asm("{ .reg .u64 t; cvta.to.shared.u64 t, %1; cvt.u32.u64 %0, t; }" : "=r"(a) : "l"(p));
    return a;
}
// blocked SW128 byte offset for bf16 (row, k), ROWS-row tile
template <int ROWS>
__device__ __forceinline__ uint32_t aoff(int row, int k) {
    uint32_t b = ((uint32_t)(row >> 3) << 10) + (uint32_t)(k >> 6) * (uint32_t)(ROWS * 128)
               + ((uint32_t)(row & 7) << 7) + ((uint32_t)(k & 63) << 1);
    return b ^ ((b >> 3) & 0x70);
}
__device__ __forceinline__ void split2(float v0, float v1, uint32_t& hw, uint32_t& lw) {
    __nv_bfloat16 h0 = __float2bfloat16(v0), h1 = __float2bfloat16(v1);
    __nv_bfloat16 l0 = __float2bfloat16(v0 - __bfloat162float(h0));
    __nv_bfloat16 l1 = __float2bfloat16(v1 - __bfloat162float(h1));
    hw = (uint32_t)__bfloat16_as_ushort(h0) | ((uint32_t)__bfloat16_as_ushort(h1) << 16);
    lw = (uint32_t)__bfloat16_as_ushort(l0) | ((uint32_t)__bfloat16_as_ushort(l1) << 16);
}
__device__ __forceinline__ void store_pair2(char* Ah, char* Al, uint32_t off,
                                            float v0, float v1) {
    uint32_t hw, lw;
    split2(v0, v1, hw, lw);
    *(uint32_t*)(Ah + off) = hw;
    *(uint32_t*)(Al + off) = lw;
}
__device__ __forceinline__ void ldsm_x4(uint32_t* r, uint32_t addr) {
    asm volatile("ldmatrix.sync.aligned.m8n8.x4.shared.b16 {%0,%1,%2,%3}, [%4];"
                 : "=r"(r[0]), "=r"(r[1]), "=r"(r[2]), "=r"(r[3]) : "r"(addr));
}
__device__ __forceinline__ void mma_bf16(float* c, const uint32_t* a, const uint32_t* b) {
    asm volatile(
        "mma.sync.aligned.m16n8k16.row.col.f32.bf16.bf16.f32 "
        "{%0,%1,%2,%3}, {%4,%5,%6,%7}, {%8,%9}, {%0,%1,%2,%3};"
        : "+f"(c[0]), "+f"(c[1]), "+f"(c[2]), "+f"(c[3])
        : "r"(a[0]), "r"(a[1]), "r"(a[2]), "r"(a[3]), "r"(b[0]), "r"(b[1]));
}

// One emulated-fp32 layer entirely in registers. A frags in ah/al, B frags from
// global (L1-hot, coalesced LDG.128). acc = Ah*Bh + Ah*Bl + Al*Bh, 16 n-tiles.
template <int KS>
__device__ __forceinline__ void layer_reg(const uint4* __restrict__ fH,
                                          const uint4* __restrict__ fL,
                                          const uint32_t ah[][4], const uint32_t al[][4],
                                          float acc[16][4], int lane) {
#pragma unroll
    for (int i = 0; i < 16; i++) {
        acc[i][0] = 0.f; acc[i][1] = 0.f; acc[i][2] = 0.f; acc[i][3] = 0.f;
    }
#pragma unroll
    for (int ks = 0; ks < KS; ks++) {
#pragma unroll
        for (int np = 0; np < 8; np++) {
            const uint4 h4 = fH[(ks * 8 + np) * 32 + lane];
            const uint4 l4 = fL[(ks * 8 + np) * 32 + lane];
            const uint32_t bh[4] = {h4.x, h4.y, h4.z, h4.w};
            const uint32_t bl[4] = {l4.x, l4.y, l4.z, l4.w};
            mma_bf16(acc[2 * np],     ah[ks], bh);
            mma_bf16(acc[2 * np + 1], ah[ks], bh + 2);
            mma_bf16(acc[2 * np],     ah[ks], bl);
            mma_bf16(acc[2 * np + 1], ah[ks], bl + 2);
            mma_bf16(acc[2 * np],     al[ks], bh);
            mma_bf16(acc[2 * np + 1], al[ks], bh + 2);
        }
    }
}

// acc (C frag, 16 n-tiles) + bias -> relu -> hi/lo A frags for next layer (k=128).
// Thread-local: C layout of n-tile pair (2ks,2ks+1) == A layout of k-step ks.
__device__ __forceinline__ void cvt_reg(const float acc[16][4], const float* sBias,
                                        int lane, uint32_t ah[][4], uint32_t al[][4]) {
    const int t2 = (lane & 3) * 2;
#pragma unroll
    for (int nt = 0; nt < 16; nt++) {
        const float2 b = *(const float2*)(sBias + nt * 8 + t2);
        const float v0 = fmaxf(acc[nt][0] + b.x, 0.f);
        const float v1 = fmaxf(acc[nt][1] + b.y, 0.f);
        const float v2 = fmaxf(acc[nt][2] + b.x, 0.f);
        const float v3 = fmaxf(acc[nt][3] + b.y, 0.f);
        uint32_t h0, l0, h1, l1;
        split2(v0, v1, h0, l0);
        split2(v2, v3, h1, l1);
        const int ks = nt >> 1, o = (nt & 1) * 2;
        ah[ks][o] = h0; ah[ks][o + 1] = h1;
        al[ks][o] = l0; al[ks][o + 1] = l1;
    }
}

// ---------------- prep kernels ----------------
__global__ void detect_kernel(const unsigned* __restrict__ p, int E) {
    if (threadIdx.x == 0) g_is64 = 1;
    __syncthreads();
    const int n = E < 2048 ? E : 2048;
    bool nz = false;
    for (int i = threadIdx.x; i < n; i += 256)
        if (p[2 * i + 1] != 0) nz = true;
    if (nz) g_is64 = 0;
}
__global__ void zero_kernel(long long total) {
    long long i = (long long)blockIdx.x * blockDim.x + threadIdx.x;
    const long long stride = (long long)gridDim.x * blockDim.x;
    for (; i < total; i += stride) g_agg[i] = 0.f;
    if (blockIdx.x == 0 && threadIdx.x < 128) {
        g_esum[threadIdx.x] = 0.f;
        g_nsum[threadIdx.x] = 0.f;
    }
}
// Build B fragments: w[K][128] -> per-(ks,np,lane) uint4 in mma.sync B layout.
__global__ void prep_frag(const float* w0, const float* w1, const float* w2, const float* w3,
                          const float* w4, const float* w5, const float* w6, const float* w7) {
    const float* ws[8] = {w0, w1, w2, w3, w4, w5, w6, w7};
    const int KS[8] = {4, 8, 8, 8, 12, 8, 8, 8};
    const int KR[8] = {64, 128, 128, 128, 160, 128, 128, 128};
    const int s = blockIdx.x, ks = blockIdx.y;
    if (ks >= KS[s]) return;
    const float* w = ws[s];
    const int kr = KR[s];
    const int np = threadIdx.x >> 5, lane = threadIdx.x & 31;
    const int t = lane & 3, gg = lane >> 2;
    const int kb = ks * 16 + 2 * t;
    uint32_t h[4], l[4];
#pragma unroll
    for (int r = 0; r < 4; r++) {
        const int n = (np * 2 + (r >> 1)) * 8 + gg;
        const int k = kb + (r & 1) * 8;
        const float v0 = (k < kr)     ? w[k * 128 + n]       : 0.f;
        const float v1 = (k + 1 < kr) ? w[(k + 1) * 128 + n] : 0.f;
        split2(v0, v1, h[r], l[r]);
    }
    const int idx = (ks * 8 + np) * 32 + lane;
    g_FH[s][idx] = make_uint4(h[0], h[1], h[2], h[3]);
    g_FL[s][idx] = make_uint4(l[0], l[1], l[2], l[3]);
}

// ---------------- edge kernel: 64 rows/block, 128 threads, no layer barriers ----------------
__global__ void __launch_bounds__(128, 3)
edge_kernel(const float* __restrict__ x, const float* __restrict__ ea,
            const float* __restrict__ u, const void* __restrict__ ei,
            const float* __restrict__ b1, const float* __restrict__ b2,
            const float* __restrict__ b3, const float* __restrict__ b4,
            float* __restrict__ e_out, int N, int E) {
    __shared__ __align__(128) char sAh[64 * 128];   // 64 rows x 64 k bf16
    __shared__ __align__(128) char sAl[64 * 128];
    __shared__ float sBias[4][128];
    __shared__ int sSrc[64], sDst[64];

    const int tid = threadIdx.x, wid = tid >> 5, lane = tid & 31;
    const int eBase = blockIdx.x * 64;
    const int is64 = g_is64;
    const float* bs[4] = {b1, b2, b3, b4};

    for (int i = tid; i < 64; i += 128) {
        int e = eBase + i;
        int s = 0, d = 0;
        if (e < E) {
            if (is64) { const long long* q = (const long long*)ei; s = (int)q[e]; d = (int)q[E + e]; }
            else      { const int* q = (const int*)ei;             s = q[e];      d = q[E + e]; }
        }
        sSrc[i] = s; sDst[i] = d;
    }
    for (int i = tid; i < 512; i += 128) sBias[i >> 7][i & 127] = bs[i >> 7][i & 127];
    __syncthreads();

    // stage layer-1 A: concat(ea, x[src], x[dst], u), K=64
    for (int i = tid; i < 64 * 32; i += 128) {
        const int row = i & 63, k = (i >> 6) * 2;
        const int e = eBase + row;
        float v0 = 0.f, v1 = 0.f;
        if (e < E) {
            if (k < 16)      { v0 = ea[(long long)e * 16 + k];  v1 = ea[(long long)e * 16 + k + 1]; }
            else if (k < 32) { int s = sSrc[row]; v0 = x[(long long)s * 16 + k - 16]; v1 = x[(long long)s * 16 + k - 15]; }
            else if (k < 48) { int d = sDst[row]; v0 = x[(long long)d * 16 + k - 32]; v1 = x[(long long)d * 16 + k - 31]; }
            else             { v0 = u[k - 48];   v1 = u[k - 47]; }
        }
        store_pair2(sAh, sAl, aoff<64>(row, k), v0, v1);
    }
    __syncthreads();

    // layer-1 A frags via ldmatrix; then the whole chain is register-resident.
    const int mrow0 = wid * 16;
    const int aRow = lane & 15, aKc = (lane >> 4) * 8;
    const uint32_t ahB = s2u(sAh), alB = s2u(sAl);
    uint32_t ah[8][4], al[8][4];
#pragma unroll
    for (int ks = 0; ks < 4; ks++) {
        const uint32_t off = aoff<64>(mrow0 + aRow, ks * 16 + aKc);
        ldsm_x4(ah[ks], ahB + off);
        ldsm_x4(al[ks], alB + off);
    }

    float acc[16][4];
    layer_reg<4>(g_FH[0], g_FL[0], ah, al, acc, lane);
    cvt_reg(acc, sBias[0], lane, ah, al);
    layer_reg<8>(g_FH[1], g_FL[1], ah, al, acc, lane);
    cvt_reg(acc, sBias[1], lane, ah, al);
    layer_reg<8>(g_FH[2], g_FL[2], ah, al, acc, lane);
    cvt_reg(acc, sBias[2], lane, ah, al);
    layer_reg<8>(g_FH[3], g_FL[3], ah, al, acc, lane);

    // epilogue: bias + direct STG (32B sector-aligned chunks) + segment-sum atomics
    const int g = lane >> 2, t2 = (lane & 3) * 2;
    const int r1 = mrow0 + g, r2 = r1 + 8;
    const int e1 = eBase + r1, e2 = eBase + r2;
    const int d1 = sDst[r1], d2 = sDst[r2];
    const bool ok1 = e1 < E, ok2 = e2 < E;
#pragma unroll
    for (int nt = 0; nt < 16; nt++) {
        const int col = nt * 8 + t2;
        const float2 b = *(const float2*)(&sBias[3][col]);
        if (ok1) {
            float2 v = make_float2(acc[nt][0] + b.x, acc[nt][1] + b.y);
            *(float2*)(e_out + (long long)e1 * 128 + col) = v;
            atomicAdd(&g_agg[d1 * 128 + col], v.x);
            atomicAdd(&g_agg[d1 * 128 + col + 1], v.y);
        }
        if (ok2) {
            float2 v = make_float2(acc[nt][2] + b.x, acc[nt][3] + b.y);
            *(float2*)(e_out + (long long)e2 * 128 + col) = v;
            atomicAdd(&g_agg[d2 * 128 + col], v.x);
            atomicAdd(&g_agg[d2 * 128 + col + 1], v.y);
        }
    }
}

// ---------------- node kernel: 64 rows/block, 128 threads ----------------
// dynamic smem: sAh 24KB | sAl 24KB | sBias 2KB
#define N_SMEM (49152 + 2048)
__global__ void __launch_bounds__(128, 2)
node_kernel(const float* __restrict__ x, const float* __restrict__ u,
            const float* __restrict__ b1, const float* __restrict__ b2,
            const float* __restrict__ b3, const float* __restrict__ b4,
            float* __restrict__ n_out, int N) {
    extern __shared__ __align__(128) char smn[];
    char* sAh = smn;
    char* sAl = smn + 24576;
    float* sBias = (float*)(smn + 49152);   // [4][128]

    const int tid = threadIdx.x, wid = tid >> 5, lane = tid & 31;
    const int nBase = blockIdx.x * 64;
    const float* bs[4] = {b1, b2, b3, b4};

    for (int i = tid; i < 512; i += 128) sBias[i] = bs[i >> 7][i & 127];

    // stage layer-1 A: concat(x, agg, u) padded to K=192
    for (int i = tid; i < 64 * 96; i += 128) {
        const int row = i & 63, k = (i >> 6) * 2;
        const int n = nBase + row;
        float v0 = 0.f, v1 = 0.f;
        if (n < N) {
            if (k < 16)       { v0 = x[(long long)n * 16 + k];           v1 = x[(long long)n * 16 + k + 1]; }
            else if (k < 144) { v0 = g_agg[(long long)n * 128 + k - 16]; v1 = g_agg[(long long)n * 128 + k - 15]; }
            else if (k < 160) { v0 = u[k - 144];                         v1 = u[k - 143]; }
        }
        store_pair2(sAh, sAl, aoff<64>(row, k), v0, v1);
    }
    __syncthreads();

    const int mrow0 = wid * 16;
    const int aRow = lane & 15, aKc = (lane >> 4) * 8;
    const uint32_t ahB = s2u(sAh), alB = s2u(sAl);
    uint32_t ah[12][4], al[12][4];
#pragma unroll
    for (int ks = 0; ks < 12; ks++) {
        const uint32_t off = aoff<64>(mrow0 + aRow, ks * 16 + aKc);
        ldsm_x4(ah[ks], ahB + off);
        ldsm_x4(al[ks], alB + off);
    }

    float acc[16][4];
    layer_reg<12>(g_FH[4], g_FL[4], ah, al, acc, lane);
    cvt_reg(acc, sBias + 0, lane, ah, al);
    layer_reg<8>(g_FH[5], g_FL[5], ah, al, acc, lane);
    cvt_reg(acc, sBias + 128, lane, ah, al);
    layer_reg<8>(g_FH[6], g_FL[6], ah, al, acc, lane);
    cvt_reg(acc, sBias + 256, lane, ah, al);
    layer_reg<8>(g_FH[7], g_FL[7], ah, al, acc, lane);

    const int g = lane >> 2, t2 = (lane & 3) * 2;
    const int r1 = mrow0 + g, r2 = r1 + 8;
    const int n1 = nBase + r1, n2 = nBase + r2;
    const bool ok1 = n1 < N, ok2 = n2 < N;
#pragma unroll
    for (int nt = 0; nt < 16; nt++) {
        const int col = nt * 8 + t2;
        const float2 b = *(const float2*)(sBias + 384 + col);
        if (ok1)
            *(float2*)(n_out + (long long)n1 * 128 + col) =
                make_float2(acc[nt][0] + b.x, acc[nt][1] + b.y);
        if (ok2)
            *(float2*)(n_out + (long long)n2 * 128 + col) =
                make_float2(acc[nt][2] + b.x, acc[nt][3] + b.y);
    }
}

// ---------------- reduce kernel: esum = colsum(g_agg), nsum = colsum(n_out) ----------------
__global__ void reduce_kernel(const float* __restrict__ n_out, int N) {
    const int col = threadIdx.x & 127;
    const int which = threadIdx.x >> 7;   // 0: g_agg->esum, 1: n_out->nsum
    const int rows_per = (N + gridDim.x - 1) / gridDim.x;
    const int r0 = blockIdx.x * rows_per;
    const int r1 = (r0 + rows_per < N) ? r0 + rows_per : N;
    const float* src = which ? n_out : g_agg;
    float s = 0.f;
    for (int r = r0; r < r1; r++) s += src[(long long)r * 128 + col];
    atomicAdd(which ? &g_nsum[col] : &g_esum[col], s);
}

// ---------------- global kernel ----------------
__global__ void global_kernel(const float* __restrict__ u,
                              const float* __restrict__ w1, const float* __restrict__ b1,
                              const float* __restrict__ w2, const float* __restrict__ b2,
                              const float* __restrict__ w3, const float* __restrict__ b3,
                              const float* __restrict__ w4, const float* __restrict__ b4,
                              float* __restrict__ g_out) {
    __shared__ float sIn[272];
    __shared__ float sH[128];
    const int t = threadIdx.x;  // 128 threads
    if (t < 16) sIn[t] = u[t];
    sIn[16 + t]  = g_nsum[t];
    sIn[144 + t] = g_esum[t];
    __syncthreads();

    float a = b1[t];
#pragma unroll 4
    for (int k = 0; k < 272; k++) a = fmaf(sIn[k], w1[k * 128 + t], a);
    a = fmaxf(a, 0.f);
    __syncthreads(); sH[t] = a; __syncthreads();

    a = b2[t];
#pragma unroll 4
    for (int k = 0; k < 128; k++) a = fmaf(sH[k], w2[k * 128 + t], a);
    a = fmaxf(a, 0.f);
    __syncthreads(); sH[t] = a; __syncthreads();

    a = b3[t];
#pragma unroll 4
    for (int k = 0; k < 128; k++) a = fmaf(sH[k], w3[k * 128 + t], a);
    a = fmaxf(a, 0.f);
    __syncthreads(); sH[t] = a; __syncthreads();

    a = b4[t];
#pragma unroll 4
    for (int k = 0; k < 128; k++) a = fmaf(sH[k], w4[k * 128 + t], a);
    g_out[t] = a;
}

// ---------------- host launcher ----------------
extern "C" void kernel_launch(void* const* d_in, const int* in_sizes, int n_in,
                              void* d_out, int out_size) {
    const float* x  = (const float*)d_in[0];
    const float* ea = (const float*)d_in[1];
    const float* u  = (const float*)d_in[2];
    const void*  ei = d_in[3];

    const int N = in_sizes[0] / 16;
    const int E = in_sizes[1] / 16;

    float* out   = (float*)d_out;
    float* e_out = out;
    float* n_out = out + (long long)E * 128;
    float* g_out = out + (long long)E * 128 + (long long)N * 128;

    cudaFuncSetAttribute(node_kernel, cudaFuncAttributeMaxDynamicSharedMemorySize, N_SMEM);

    detect_kernel<<<1, 256>>>((const unsigned*)ei, E);
    zero_kernel<<<1024, 256>>>((long long)N * 128);
    prep_frag<<<dim3(8, 12), 256>>>((const float*)d_in[4],  (const float*)d_in[6],
                                    (const float*)d_in[8],  (const float*)d_in[10],
                                    (const float*)d_in[12], (const float*)d_in[14],
                                    (const float*)d_in[16], (const float*)d_in[18]);
    edge_kernel<<<(E + 63) / 64, 128>>>(
        x, ea, u, ei,
        (const float*)d_in[5], (const float*)d_in[7],
        (const float*)d_in[9], (const float*)d_in[11],
        e_out, N, E);
    node_kernel<<<(N + 63) / 64, 128, N_SMEM>>>(
        x, u,
        (const float*)d_in[13], (const float*)d_in[15],
        (const float*)d_in[17], (const float*)d_in[19],
        n_out, N);
    reduce_kernel<<<100, 256>>>(n_out, N);
    global_kernel<<<1, 128>>>(
        u,
        (const float*)d_in[20], (const float*)d_in[21],
        (const float*)d_in[22], (const float*)d_in[23],
        (const float*)d_in[24], (const float*)d_in[25],
        (const float*)d_in[26], (const float*)d_in[27],
        g_out);
}

// round 8
// speedup vs baseline: 1.6809x; 1.0661x over previous
#include <cuda_runtime.h>
#include <cuda_bf16.h>
#include <cstdint>

#define MAX_NODES 50000

// ---------------- device scratch ----------------
__device__ float g_agg[MAX_NODES * 128];
__device__ float g_esum[128];
__device__ float g_nsum[128];
__device__ int   g_is64;
// B operands pre-shuffled into mma.sync fragment order, H/L interleaved:
// [layer][((ks*8+np)*32+lane)*2 + {0:H,1:L}]
__device__ __align__(32) uint4 g_F[8][12 * 8 * 32 * 2];

// ---------------- helpers ----------------
__device__ __forceinline__ uint32_t s2u(const void* p) {
    uint32_t a;
    asm("{ .reg .u64 t; cvta.to.shared.u64 t, %1; cvt.u32.u64 %0, t; }" : "=r"(a) : "l"(p));
    return a;
}
// blocked SW128 byte offset for bf16 (row, k), ROWS-row tile
template <int ROWS>
__device__ __forceinline__ uint32_t aoff(int row, int k) {
    uint32_t b = ((uint32_t)(row >> 3) << 10) + (uint32_t)(k >> 6) * (uint32_t)(ROWS * 128)
               + ((uint32_t)(row & 7) << 7) + ((uint32_t)(k & 63) << 1);
    return b ^ ((b >> 3) & 0x70);
}
__device__ __forceinline__ void split2(float v0, float v1, uint32_t& hw, uint32_t& lw) {
    __nv_bfloat16 h0 = __float2bfloat16(v0), h1 = __float2bfloat16(v1);
    __nv_bfloat16 l0 = __float2bfloat16(v0 - __bfloat162float(h0));
    __nv_bfloat16 l1 = __float2bfloat16(v1 - __bfloat162float(h1));
    hw = (uint32_t)__bfloat16_as_ushort(h0) | ((uint32_t)__bfloat16_as_ushort(h1) << 16);
    lw = (uint32_t)__bfloat16_as_ushort(l0) | ((uint32_t)__bfloat16_as_ushort(l1) << 16);
}
__device__ __forceinline__ void store_pair2(char* Ah, char* Al, uint32_t off,
                                            float v0, float v1) {
    uint32_t hw, lw;
    split2(v0, v1, hw, lw);
    *(uint32_t*)(Ah + off) = hw;
    *(uint32_t*)(Al + off) = lw;
}
__device__ __forceinline__ void ldsm_x4(uint32_t* r, uint32_t addr) {
    asm volatile("ldmatrix.sync.aligned.m8n8.x4.shared.b16 {%0,%1,%2,%3}, [%4];"
                 : "=r"(r[0]), "=r"(r[1]), "=r"(r[2]), "=r"(r[3]) : "r"(addr));
}
__device__ __forceinline__ void mma_bf16(float* c, const uint32_t* a, const uint32_t* b) {
    asm volatile(
        "mma.sync.aligned.m16n8k16.row.col.f32.bf16.bf16.f32 "
        "{%0,%1,%2,%3}, {%4,%5,%6,%7}, {%8,%9}, {%0,%1,%2,%3};"
        : "+f"(c[0]), "+f"(c[1]), "+f"(c[2]), "+f"(c[3])
        : "r"(a[0]), "r"(a[1]), "r"(a[2]), "r"(a[3]), "r"(b[0]), "r"(b[1]));
}
__device__ __forceinline__ void red2(float* addr, float v0, float v1) {
    asm volatile("red.global.add.v2.f32 [%0], {%1,%2};"
                 :: "l"(addr), "f"(v0), "f"(v1) : "memory");
}

// One emulated-fp32 layer entirely in registers. A frags in ah/al, B frags from
// global (L1-hot, H/L interleaved 32B). acc = Ah*Bh + Ah*Bl + Al*Bh, 16 n-tiles.
template <int KS>
__device__ __forceinline__ void layer_reg(const uint4* __restrict__ f,
                                          const uint32_t ah[][4], const uint32_t al[][4],
                                          float acc[16][4], int lane) {
#pragma unroll
    for (int i = 0; i < 16; i++) {
        acc[i][0] = 0.f; acc[i][1] = 0.f; acc[i][2] = 0.f; acc[i][3] = 0.f;
    }
#pragma unroll
    for (int ks = 0; ks < KS; ks++) {
#pragma unroll
        for (int np = 0; np < 8; np++) {
            const int idx = ((ks * 8 + np) * 32 + lane) * 2;
            const uint4 h4 = f[idx];
            const uint4 l4 = f[idx + 1];
            const uint32_t bh[4] = {h4.x, h4.y, h4.z, h4.w};
            const uint32_t bl[4] = {l4.x, l4.y, l4.z, l4.w};
            mma_bf16(acc[2 * np],     ah[ks], bh);
            mma_bf16(acc[2 * np + 1], ah[ks], bh + 2);
            mma_bf16(acc[2 * np],     ah[ks], bl);
            mma_bf16(acc[2 * np + 1], ah[ks], bl + 2);
            mma_bf16(acc[2 * np],     al[ks], bh);
            mma_bf16(acc[2 * np + 1], al[ks], bh + 2);
        }
    }
}

// acc (C frag, 16 n-tiles) + bias -> relu -> hi/lo A frags for next layer (k=128).
__device__ __forceinline__ void cvt_reg(const float acc[16][4], const float* sBias,
                                        int lane, uint32_t ah[][4], uint32_t al[][4]) {
    const int t2 = (lane & 3) * 2;
#pragma unroll
    for (int nt = 0; nt < 16; nt++) {
        const float2 b = *(const float2*)(sBias + nt * 8 + t2);
        const float v0 = fmaxf(acc[nt][0] + b.x, 0.f);
        const float v1 = fmaxf(acc[nt][1] + b.y, 0.f);
        const float v2 = fmaxf(acc[nt][2] + b.x, 0.f);
        const float v3 = fmaxf(acc[nt][3] + b.y, 0.f);
        uint32_t h0, l0, h1, l1;
        split2(v0, v1, h0, l0);
        split2(v2, v3, h1, l1);
        const int ks = nt >> 1, o = (nt & 1) * 2;
        ah[ks][o] = h0; ah[ks][o + 1] = h1;
        al[ks][o] = l0; al[ks][o + 1] = l1;
    }
}

// ---------------- prep kernels ----------------
__global__ void detect_kernel(const unsigned* __restrict__ p, int E) {
    if (threadIdx.x == 0) g_is64 = 1;
    __syncthreads();
    const int n = E < 2048 ? E : 2048;
    bool nz = false;
    for (int i = threadIdx.x; i < n; i += 256)
        if (p[2 * i + 1] != 0) nz = true;
    if (nz) g_is64 = 0;
}
__global__ void zero_kernel(long long total) {
    long long i = (long long)blockIdx.x * blockDim.x + threadIdx.x;
    const long long stride = (long long)gridDim.x * blockDim.x;
    for (; i < total; i += stride) g_agg[i] = 0.f;
    if (blockIdx.x == 0 && threadIdx.x < 128) {
        g_esum[threadIdx.x] = 0.f;
        g_nsum[threadIdx.x] = 0.f;
    }
}
// Build B fragments: w[K][128] -> per-(ks,np,lane) H/L uint4 pair in mma.sync B layout.
__global__ void prep_frag(const float* w0, const float* w1, const float* w2, const float* w3,
                          const float* w4, const float* w5, const float* w6, const float* w7) {
    const float* ws[8] = {w0, w1, w2, w3, w4, w5, w6, w7};
    const int KS[8] = {4, 8, 8, 8, 12, 8, 8, 8};
    const int KR[8] = {64, 128, 128, 128, 160, 128, 128, 128};
    const int s = blockIdx.x, ks = blockIdx.y;
    if (ks >= KS[s]) return;
    const float* w = ws[s];
    const int kr = KR[s];
    const int np = threadIdx.x >> 5, lane = threadIdx.x & 31;
    const int t = lane & 3, gg = lane >> 2;
    const int kb = ks * 16 + 2 * t;
    uint32_t h[4], l[4];
#pragma unroll
    for (int r = 0; r < 4; r++) {
        const int n = (np * 2 + (r >> 1)) * 8 + gg;
        const int k = kb + (r & 1) * 8;
        const float v0 = (k < kr)     ? w[k * 128 + n]       : 0.f;
        const float v1 = (k + 1 < kr) ? w[(k + 1) * 128 + n] : 0.f;
        split2(v0, v1, h[r], l[r]);
    }
    const int idx = ((ks * 8 + np) * 32 + lane) * 2;
    g_F[s][idx]     = make_uint4(h[0], h[1], h[2], h[3]);
    g_F[s][idx + 1] = make_uint4(l[0], l[1], l[2], l[3]);
}

// ---------------- edge kernel: 64 rows/block, 128 threads, no layer barriers ----------------
__global__ void __launch_bounds__(128, 3)
edge_kernel(const float* __restrict__ x, const float* __restrict__ ea,
            const float* __restrict__ u, const void* __restrict__ ei,
            const float* __restrict__ b1, const float* __restrict__ b2,
            const float* __restrict__ b3, const float* __restrict__ b4,
            float* __restrict__ e_out, int N, int E) {
    __shared__ __align__(128) char sAh[64 * 128];   // 64 rows x 64 k bf16
    __shared__ __align__(128) char sAl[64 * 128];
    __shared__ float sBias[4][128];
    __shared__ int sSrc[64], sDst[64];

    const int tid = threadIdx.x, wid = tid >> 5, lane = tid & 31;
    const int eBase = blockIdx.x * 64;
    const int is64 = g_is64;
    const float* bs[4] = {b1, b2, b3, b4};

    for (int i = tid; i < 64; i += 128) {
        int e = eBase + i;
        int s = 0, d = 0;
        if (e < E) {
            if (is64) { const long long* q = (const long long*)ei; s = (int)q[e]; d = (int)q[E + e]; }
            else      { const int* q = (const int*)ei;             s = q[e];      d = q[E + e]; }
        }
        sSrc[i] = s; sDst[i] = d;
    }
    for (int i = tid; i < 512; i += 128) sBias[i >> 7][i & 127] = bs[i >> 7][i & 127];
    __syncthreads();

    // stage layer-1 A: concat(ea, x[src], x[dst], u), K=64
    for (int i = tid; i < 64 * 32; i += 128) {
        const int row = i & 63, k = (i >> 6) * 2;
        const int e = eBase + row;
        float v0 = 0.f, v1 = 0.f;
        if (e < E) {
            if (k < 16)      { v0 = ea[(long long)e * 16 + k];  v1 = ea[(long long)e * 16 + k + 1]; }
            else if (k < 32) { int s = sSrc[row]; v0 = x[(long long)s * 16 + k - 16]; v1 = x[(long long)s * 16 + k - 15]; }
            else if (k < 48) { int d = sDst[row]; v0 = x[(long long)d * 16 + k - 32]; v1 = x[(long long)d * 16 + k - 31]; }
            else             { v0 = u[k - 48];   v1 = u[k - 47]; }
        }
        store_pair2(sAh, sAl, aoff<64>(row, k), v0, v1);
    }
    __syncthreads();

    // layer-1 A frags via ldmatrix; then the whole chain is register-resident.
    const int mrow0 = wid * 16;
    const int aRow = lane & 15, aKc = (lane >> 4) * 8;
    const uint32_t ahB = s2u(sAh), alB = s2u(sAl);
    uint32_t ah[8][4], al[8][4];
#pragma unroll
    for (int ks = 0; ks < 4; ks++) {
        const uint32_t off = aoff<64>(mrow0 + aRow, ks * 16 + aKc);
        ldsm_x4(ah[ks], ahB + off);
        ldsm_x4(al[ks], alB + off);
    }

    float acc[16][4];
    layer_reg<4>(g_F[0], ah, al, acc, lane);
    cvt_reg(acc, sBias[0], lane, ah, al);
    layer_reg<8>(g_F[1], ah, al, acc, lane);
    cvt_reg(acc, sBias[1], lane, ah, al);
    layer_reg<8>(g_F[2], ah, al, acc, lane);
    cvt_reg(acc, sBias[2], lane, ah, al);
    layer_reg<8>(g_F[3], ah, al, acc, lane);

    // epilogue: bias + direct STG + vector segment-sum atomics (red.v2)
    const int g = lane >> 2, t2 = (lane & 3) * 2;
    const int r1 = mrow0 + g, r2 = r1 + 8;
    const int e1 = eBase + r1, e2 = eBase + r2;
    const int d1 = sDst[r1], d2 = sDst[r2];
    const bool ok1 = e1 < E, ok2 = e2 < E;
#pragma unroll
    for (int nt = 0; nt < 16; nt++) {
        const int col = nt * 8 + t2;
        const float2 b = *(const float2*)(&sBias[3][col]);
        if (ok1) {
            float2 v = make_float2(acc[nt][0] + b.x, acc[nt][1] + b.y);
            *(float2*)(e_out + (long long)e1 * 128 + col) = v;
            red2(&g_agg[d1 * 128 + col], v.x, v.y);
        }
        if (ok2) {
            float2 v = make_float2(acc[nt][2] + b.x, acc[nt][3] + b.y);
            *(float2*)(e_out + (long long)e2 * 128 + col) = v;
            red2(&g_agg[d2 * 128 + col], v.x, v.y);
        }
    }
}

// ---------------- node kernel: 64 rows/block, 128 threads ----------------
// dynamic smem: sAh 24KB | sAl 24KB | sBias 2KB
#define N_SMEM (49152 + 2048)
__global__ void __launch_bounds__(128, 2)
node_kernel(const float* __restrict__ x, const float* __restrict__ u,
            const float* __restrict__ b1, const float* __restrict__ b2,
            const float* __restrict__ b3, const float* __restrict__ b4,
            float* __restrict__ n_out, int N) {
    extern __shared__ __align__(128) char smn[];
    char* sAh = smn;
    char* sAl = smn + 24576;
    float* sBias = (float*)(smn + 49152);   // [4][128]

    const int tid = threadIdx.x, wid = tid >> 5, lane = tid & 31;
    const int nBase = blockIdx.x * 64;
    const int lim = ((N - nBase) < 64) ? (N - nBase) : 64;
    const float* bs[4] = {b1, b2, b3, b4};

    for (int i = tid; i < 512; i += 128) sBias[i] = bs[i >> 7][i & 127];

    // esum contribution: column sums of this block's g_agg rows
    {
        float se = 0.f;
        for (int r = 0; r < lim; r++) se += g_agg[(long long)(nBase + r) * 128 + tid];
        atomicAdd(&g_esum[tid], se);
    }

    // stage layer-1 A: concat(x, agg, u) padded to K=192
    for (int i = tid; i < 64 * 96; i += 128) {
        const int row = i & 63, k = (i >> 6) * 2;
        const int n = nBase + row;
        float v0 = 0.f, v1 = 0.f;
        if (n < N) {
            if (k < 16)       { v0 = x[(long long)n * 16 + k];           v1 = x[(long long)n * 16 + k + 1]; }
            else if (k < 144) { v0 = g_agg[(long long)n * 128 + k - 16]; v1 = g_agg[(long long)n * 128 + k - 15]; }
            else if (k < 160) { v0 = u[k - 144];                         v1 = u[k - 143]; }
        }
        store_pair2(sAh, sAl, aoff<64>(row, k), v0, v1);
    }
    __syncthreads();

    const int mrow0 = wid * 16;
    const int aRow = lane & 15, aKc = (lane >> 4) * 8;
    const uint32_t ahB = s2u(sAh), alB = s2u(sAl);
    uint32_t ah[12][4], al[12][4];
#pragma unroll
    for (int ks = 0; ks < 12; ks++) {
        const uint32_t off = aoff<64>(mrow0 + aRow, ks * 16 + aKc);
        ldsm_x4(ah[ks], ahB + off);
        ldsm_x4(al[ks], alB + off);
    }

    float acc[16][4];
    layer_reg<12>(g_F[4], ah, al, acc, lane);
    cvt_reg(acc, sBias + 0, lane, ah, al);
    layer_reg<8>(g_F[5], ah, al, acc, lane);
    cvt_reg(acc, sBias + 128, lane, ah, al);
    layer_reg<8>(g_F[6], ah, al, acc, lane);
    cvt_reg(acc, sBias + 256, lane, ah, al);
    layer_reg<8>(g_F[7], ah, al, acc, lane);

    const int g = lane >> 2, t2 = (lane & 3) * 2;
    const int r1 = mrow0 + g, r2 = r1 + 8;
    const int n1 = nBase + r1, n2 = nBase + r2;
    const bool ok1 = n1 < N, ok2 = n2 < N;
#pragma unroll
    for (int nt = 0; nt < 16; nt++) {
        const int col = nt * 8 + t2;
        const float2 b = *(const float2*)(sBias + 384 + col);
        if (ok1)
            *(float2*)(n_out + (long long)n1 * 128 + col) =
                make_float2(acc[nt][0] + b.x, acc[nt][1] + b.y);
        if (ok2)
            *(float2*)(n_out + (long long)n2 * 128 + col) =
                make_float2(acc[nt][2] + b.x, acc[nt][3] + b.y);
    }

    // nsum contribution: re-read this block's n_out rows (L2-hot), column sums
    __syncthreads();
    {
        float sn = 0.f;
        for (int r = 0; r < lim; r++) sn += n_out[(long long)(nBase + r) * 128 + tid];
        atomicAdd(&g_nsum[tid], sn);
    }
}

// ---------------- global kernel ----------------
__global__ void global_kernel(const float* __restrict__ u,
                              const float* __restrict__ w1, const float* __restrict__ b1,
                              const float* __restrict__ w2, const float* __restrict__ b2,
                              const float* __restrict__ w3, const float* __restrict__ b3,
                              const float* __restrict__ w4, const float* __restrict__ b4,
                              float* __restrict__ g_out) {
    __shared__ float sIn[272];
    __shared__ float sH[128];
    const int t = threadIdx.x;  // 128 threads
    if (t < 16) sIn[t] = u[t];
    sIn[16 + t]  = g_nsum[t];
    sIn[144 + t] = g_esum[t];
    __syncthreads();

    float a = b1[t];
#pragma unroll 4
    for (int k = 0; k < 272; k++) a = fmaf(sIn[k], w1[k * 128 + t], a);
    a = fmaxf(a, 0.f);
    __syncthreads(); sH[t] = a; __syncthreads();

    a = b2[t];
#pragma unroll 4
    for (int k = 0; k < 128; k++) a = fmaf(sH[k], w2[k * 128 + t], a);
    a = fmaxf(a, 0.f);
    __syncthreads(); sH[t] = a; __syncthreads();

    a = b3[t];
#pragma unroll 4
    for (int k = 0; k < 128; k++) a = fmaf(sH[k], w3[k * 128 + t], a);
    a = fmaxf(a, 0.f);
    __syncthreads(); sH[t] = a; __syncthreads();

    a = b4[t];
#pragma unroll 4
    for (int k = 0; k < 128; k++) a = fmaf(sH[k], w4[k * 128 + t], a);
    g_out[t] = a;
}

// ---------------- host launcher ----------------
extern "C" void kernel_launch(void* const* d_in, const int* in_sizes, int n_in,
                              void* d_out, int out_size) {
    const float* x  = (const float*)d_in[0];
    const float* ea = (const float*)d_in[1];
    const float* u  = (const float*)d_in[2];
    const void*  ei = d_in[3];

    const int N = in_sizes[0] / 16;
    const int E = in_sizes[1] / 16;

    float* out   = (float*)d_out;
    float* e_out = out;
    float* n_out = out + (long long)E * 128;
    float* g_out = out + (long long)E * 128 + (long long)N * 128;

    cudaFuncSetAttribute(node_kernel, cudaFuncAttributeMaxDynamicSharedMemorySize, N_SMEM);

    detect_kernel<<<1, 256>>>((const unsigned*)ei, E);
    zero_kernel<<<1024, 256>>>((long long)N * 128);
    prep_frag<<<dim3(8, 12), 256>>>((const float*)d_in[4],  (const float*)d_in[6],
                                    (const float*)d_in[8],  (const float*)d_in[10],
                                    (const float*)d_in[12], (const float*)d_in[14],
                                    (const float*)d_in[16], (const float*)d_in[18]);
    edge_kernel<<<(E + 63) / 64, 128>>>(
        x, ea, u, ei,
        (const float*)d_in[5], (const float*)d_in[7],
        (const float*)d_in[9], (const float*)d_in[11],
        e_out, N, E);
    node_kernel<<<(N + 63) / 64, 128, N_SMEM>>>(
        x, u,
        (const float*)d_in[13], (const float*)d_in[15],
        (const float*)d_in[17], (const float*)d_in[19],
        n_out, N);
    global_kernel<<<1, 128>>>(
        u,
        (const float*)d_in[20], (const float*)d_in[21],
        (const float*)d_in[22], (const float*)d_in[23],
        (const float*)d_in[24], (const float*)d_in[25],
        (const float*)d_in[26], (const float*)d_in[27],
        g_out);
}

// round 9
// speedup vs baseline: 1.9687x; 1.1712x over previous
#include <cuda_runtime.h>
#include <cuda_bf16.h>
#include <cstdint>

#define MAX_NODES 50000

// ---------------- device scratch ----------------
__device__ float g_agg[MAX_NODES * 128];
__device__ float g_esum[128];
__device__ float g_nsum[128];
__device__ int   g_is64;
// B operands pre-shuffled into mma.sync fragment order, H/L interleaved:
// [layer][((ks*8+np)*32+lane)*2 + {0:H,1:L}]
__device__ __align__(32) uint4 g_F[8][12 * 8 * 32 * 2];

// ---------------- helpers ----------------
__device__ __forceinline__ void split2(float v0, float v1, uint32_t& hw, uint32_t& lw) {
    __nv_bfloat16 h0 = __float2bfloat16(v0), h1 = __float2bfloat16(v1);
    __nv_bfloat16 l0 = __float2bfloat16(v0 - __bfloat162float(h0));
    __nv_bfloat16 l1 = __float2bfloat16(v1 - __bfloat162float(h1));
    hw = (uint32_t)__bfloat16_as_ushort(h0) | ((uint32_t)__bfloat16_as_ushort(h1) << 16);
    lw = (uint32_t)__bfloat16_as_ushort(l0) | ((uint32_t)__bfloat16_as_ushort(l1) << 16);
}
__device__ __forceinline__ void mma_bf16(float* c, const uint32_t* a, const uint32_t* b) {
    asm volatile(
        "mma.sync.aligned.m16n8k16.row.col.f32.bf16.bf16.f32 "
        "{%0,%1,%2,%3}, {%4,%5,%6,%7}, {%8,%9}, {%0,%1,%2,%3};"
        : "+f"(c[0]), "+f"(c[1]), "+f"(c[2]), "+f"(c[3])
        : "r"(a[0]), "r"(a[1]), "r"(a[2]), "r"(a[3]), "r"(b[0]), "r"(b[1]));
}
__device__ __forceinline__ void red2(float* addr, float v0, float v1) {
    asm volatile("red.global.add.v2.f32 [%0], {%1,%2};"
                 :: "l"(addr), "f"(v0), "f"(v1) : "memory");
}

// Direct A-fragment load: two source rows (p1: rows g, p2: rows g+8), 16 cols.
__device__ __forceinline__ void load_afrag(const float* p1, const float* p2, int t2,
                                           bool ok1, bool ok2,
                                           uint32_t ah[4], uint32_t al[4]) {
    float2 z = make_float2(0.f, 0.f);
    float2 v00 = ok1 ? *(const float2*)(p1 + t2)     : z;
    float2 v01 = ok1 ? *(const float2*)(p1 + 8 + t2) : z;
    float2 v10 = ok2 ? *(const float2*)(p2 + t2)     : z;
    float2 v11 = ok2 ? *(const float2*)(p2 + 8 + t2) : z;
    split2(v00.x, v00.y, ah[0], al[0]);
    split2(v10.x, v10.y, ah[1], al[1]);
    split2(v01.x, v01.y, ah[2], al[2]);
    split2(v11.x, v11.y, ah[3], al[3]);
}

// One emulated-fp32 layer in registers with 1-deep B prefetch.
// acc = Ah*Bh + Ah*Bl + Al*Bh, 16 n-tiles, KS k-steps.
template <int KS>
__device__ __forceinline__ void layer_reg(const uint4* __restrict__ f,
                                          const uint32_t ah[][4], const uint32_t al[][4],
                                          float acc[16][4], int lane) {
    const uint4* p = f + lane * 2;
#pragma unroll
    for (int i = 0; i < 16; i++) {
        acc[i][0] = 0.f; acc[i][1] = 0.f; acc[i][2] = 0.f; acc[i][3] = 0.f;
    }
    uint4 h4 = p[0], l4 = p[1];
#pragma unroll
    for (int i = 0; i < KS * 8; i++) {
        const int ks = i >> 3, np = i & 7;
        uint4 h4n = h4, l4n = l4;
        if (i + 1 < KS * 8) {
            h4n = p[(i + 1) * 64];
            l4n = p[(i + 1) * 64 + 1];
        }
        const uint32_t bh[4] = {h4.x, h4.y, h4.z, h4.w};
        const uint32_t bl[4] = {l4.x, l4.y, l4.z, l4.w};
        mma_bf16(acc[2 * np],     ah[ks], bh);
        mma_bf16(acc[2 * np + 1], ah[ks], bh + 2);
        mma_bf16(acc[2 * np],     ah[ks], bl);
        mma_bf16(acc[2 * np + 1], ah[ks], bl + 2);
        mma_bf16(acc[2 * np],     al[ks], bh);
        mma_bf16(acc[2 * np + 1], al[ks], bh + 2);
        h4 = h4n; l4 = l4n;
    }
}

// acc (C frag, 16 n-tiles) + bias -> relu -> hi/lo A frags for next layer (k=128).
__device__ __forceinline__ void cvt_reg(const float acc[16][4], const float* sBias,
                                        int lane, uint32_t ah[][4], uint32_t al[][4]) {
    const int t2 = (lane & 3) * 2;
#pragma unroll
    for (int nt = 0; nt < 16; nt++) {
        const float2 b = *(const float2*)(sBias + nt * 8 + t2);
        const float v0 = fmaxf(acc[nt][0] + b.x, 0.f);
        const float v1 = fmaxf(acc[nt][1] + b.y, 0.f);
        const float v2 = fmaxf(acc[nt][2] + b.x, 0.f);
        const float v3 = fmaxf(acc[nt][3] + b.y, 0.f);
        uint32_t h0, l0, h1, l1;
        split2(v0, v1, h0, l0);
        split2(v2, v3, h1, l1);
        const int ks = nt >> 1, o = (nt & 1) * 2;
        ah[ks][o] = h0; ah[ks][o + 1] = h1;
        al[ks][o] = l0; al[ks][o + 1] = l1;
    }
}

// ---------------- prep kernels ----------------
__global__ void detect_kernel(const unsigned* __restrict__ p, int E) {
    if (threadIdx.x == 0) g_is64 = 1;
    __syncthreads();
    const int n = E < 2048 ? E : 2048;
    bool nz = false;
    for (int i = threadIdx.x; i < n; i += 256)
        if (p[2 * i + 1] != 0) nz = true;
    if (nz) g_is64 = 0;
}
__global__ void zero_kernel(long long total) {
    long long i = (long long)blockIdx.x * blockDim.x + threadIdx.x;
    const long long stride = (long long)gridDim.x * blockDim.x;
    for (; i < total; i += stride) g_agg[i] = 0.f;
    if (blockIdx.x == 0 && threadIdx.x < 128) {
        g_esum[threadIdx.x] = 0.f;
        g_nsum[threadIdx.x] = 0.f;
    }
}
// Build B fragments: w[K][128] -> per-(ks,np,lane) H/L uint4 pair in mma.sync B layout.
__global__ void prep_frag(const float* w0, const float* w1, const float* w2, const float* w3,
                          const float* w4, const float* w5, const float* w6, const float* w7) {
    const float* ws[8] = {w0, w1, w2, w3, w4, w5, w6, w7};
    const int KS[8] = {4, 8, 8, 8, 10, 8, 8, 8};
    const int KR[8] = {64, 128, 128, 128, 160, 128, 128, 128};
    const int s = blockIdx.x, ks = blockIdx.y;
    if (ks >= KS[s]) return;
    const float* w = ws[s];
    const int kr = KR[s];
    const int np = threadIdx.x >> 5, lane = threadIdx.x & 31;
    const int t = lane & 3, gg = lane >> 2;
    const int kb = ks * 16 + 2 * t;
    uint32_t h[4], l[4];
#pragma unroll
    for (int r = 0; r < 4; r++) {
        const int n = (np * 2 + (r >> 1)) * 8 + gg;
        const int k = kb + (r & 1) * 8;
        const float v0 = (k < kr)     ? w[k * 128 + n]       : 0.f;
        const float v1 = (k + 1 < kr) ? w[(k + 1) * 128 + n] : 0.f;
        split2(v0, v1, h[r], l[r]);
    }
    const int idx = ((ks * 8 + np) * 32 + lane) * 2;
    g_F[s][idx]     = make_uint4(h[0], h[1], h[2], h[3]);
    g_F[s][idx + 1] = make_uint4(l[0], l[1], l[2], l[3]);
}

// ---------------- edge kernel: 64 rows/block, 128 threads, ~2.5KB smem ----------------
__global__ void __launch_bounds__(128, 3)
edge_kernel(const float* __restrict__ x, const float* __restrict__ ea,
            const float* __restrict__ u, const void* __restrict__ ei,
            const float* __restrict__ b1, const float* __restrict__ b2,
            const float* __restrict__ b3, const float* __restrict__ b4,
            float* __restrict__ e_out, int N, int E) {
    __shared__ float sBias[4][128];
    __shared__ int sSrc[64], sDst[64];

    const int tid = threadIdx.x, wid = tid >> 5, lane = tid & 31;
    const int g = lane >> 2, t2 = (lane & 3) * 2;
    const int eBase = blockIdx.x * 64;
    const int is64 = g_is64;
    const float* bs[4] = {b1, b2, b3, b4};

    for (int i = tid; i < 64; i += 128) {
        int e = eBase + i;
        int s = 0, d = 0;
        if (e < E) {
            if (is64) { const long long* q = (const long long*)ei; s = (int)q[e]; d = (int)q[E + e]; }
            else      { const int* q = (const int*)ei;             s = q[e];      d = q[E + e]; }
        }
        sSrc[i] = s; sDst[i] = d;
    }
    for (int i = tid; i < 512; i += 128) sBias[i >> 7][i & 127] = bs[i >> 7][i & 127];
    __syncthreads();

    const int r1 = wid * 16 + g, r2 = r1 + 8;
    const int e1 = eBase + r1, e2 = eBase + r2;
    const bool ok1 = e1 < E, ok2 = e2 < E;
    const int s1 = sSrc[r1], s2 = sSrc[r2];
    const int d1 = sDst[r1], d2 = sDst[r2];

    // layer-1 A frags straight from global: ks0=ea, ks1=x[src], ks2=x[dst], ks3=u
    uint32_t ah[8][4], al[8][4];
    load_afrag(ea + (long long)e1 * 16, ea + (long long)e2 * 16, t2, ok1, ok2, ah[0], al[0]);
    load_afrag(x + (long long)s1 * 16,  x + (long long)s2 * 16,  t2, ok1, ok2, ah[1], al[1]);
    load_afrag(x + (long long)d1 * 16,  x + (long long)d2 * 16,  t2, ok1, ok2, ah[2], al[2]);
    load_afrag(u, u, t2, ok1, ok2, ah[3], al[3]);

    float acc[16][4];
    layer_reg<4>(g_F[0], ah, al, acc, lane);
    cvt_reg(acc, sBias[0], lane, ah, al);
    layer_reg<8>(g_F[1], ah, al, acc, lane);
    cvt_reg(acc, sBias[1], lane, ah, al);
    layer_reg<8>(g_F[2], ah, al, acc, lane);
    cvt_reg(acc, sBias[2], lane, ah, al);
    layer_reg<8>(g_F[3], ah, al, acc, lane);

    // epilogue: bias + direct STG + vector segment-sum atomics (red.v2)
#pragma unroll
    for (int nt = 0; nt < 16; nt++) {
        const int col = nt * 8 + t2;
        const float2 b = *(const float2*)(&sBias[3][col]);
        if (ok1) {
            float2 v = make_float2(acc[nt][0] + b.x, acc[nt][1] + b.y);
            *(float2*)(e_out + (long long)e1 * 128 + col) = v;
            red2(&g_agg[d1 * 128 + col], v.x, v.y);
        }
        if (ok2) {
            float2 v = make_float2(acc[nt][2] + b.x, acc[nt][3] + b.y);
            *(float2*)(e_out + (long long)e2 * 128 + col) = v;
            red2(&g_agg[d2 * 128 + col], v.x, v.y);
        }
    }
}

// ---------------- node kernel: 64 rows/block, 128 threads ----------------
__global__ void __launch_bounds__(128, 2)
node_kernel(const float* __restrict__ x, const float* __restrict__ u,
            const float* __restrict__ b1, const float* __restrict__ b2,
            const float* __restrict__ b3, const float* __restrict__ b4,
            float* __restrict__ n_out, int N) {
    __shared__ float sBias[4][128];

    const int tid = threadIdx.x, wid = tid >> 5, lane = tid & 31;
    const int g = lane >> 2, t2 = (lane & 3) * 2;
    const int nBase = blockIdx.x * 64;
    const int lim = ((N - nBase) < 64) ? (N - nBase) : 64;
    const float* bs[4] = {b1, b2, b3, b4};

    for (int i = tid; i < 512; i += 128) sBias[i >> 7][i & 127] = bs[i >> 7][i & 127];

    // esum contribution: column sums of this block's g_agg rows
    {
        float se = 0.f;
        for (int r = 0; r < lim; r++) se += g_agg[(long long)(nBase + r) * 128 + tid];
        atomicAdd(&g_esum[tid], se);
    }
    __syncthreads();

    const int r1 = wid * 16 + g, r2 = r1 + 8;
    const int n1 = nBase + r1, n2 = nBase + r2;
    const bool ok1 = n1 < N, ok2 = n2 < N;

    // layer-1 A frags straight from global: ks0=x, ks1-8=agg, ks9=u (K=160, 10 ks)
    uint32_t ah[10][4], al[10][4];
    load_afrag(x + (long long)n1 * 16, x + (long long)n2 * 16, t2, ok1, ok2, ah[0], al[0]);
#pragma unroll
    for (int j = 0; j < 8; j++)
        load_afrag(g_agg + (long long)n1 * 128 + j * 16,
                   g_agg + (long long)n2 * 128 + j * 16, t2, ok1, ok2, ah[1 + j], al[1 + j]);
    load_afrag(u, u, t2, ok1, ok2, ah[9], al[9]);

    float acc[16][4];
    layer_reg<10>(g_F[4], ah, al, acc, lane);
    cvt_reg(acc, sBias[0], lane, ah, al);
    layer_reg<8>(g_F[5], ah, al, acc, lane);
    cvt_reg(acc, sBias[1], lane, ah, al);
    layer_reg<8>(g_F[6], ah, al, acc, lane);
    cvt_reg(acc, sBias[2], lane, ah, al);
    layer_reg<8>(g_F[7], ah, al, acc, lane);

#pragma unroll
    for (int nt = 0; nt < 16; nt++) {
        const int col = nt * 8 + t2;
        const float2 b = *(const float2*)(&sBias[3][col]);
        if (ok1)
            *(float2*)(n_out + (long long)n1 * 128 + col) =
                make_float2(acc[nt][0] + b.x, acc[nt][1] + b.y);
        if (ok2)
            *(float2*)(n_out + (long long)n2 * 128 + col) =
                make_float2(acc[nt][2] + b.x, acc[nt][3] + b.y);
    }

    // nsum contribution: re-read this block's n_out rows (L2-hot), column sums
    __syncthreads();
    {
        float sn = 0.f;
        for (int r = 0; r < lim; r++) sn += n_out[(long long)(nBase + r) * 128 + tid];
        atomicAdd(&g_nsum[tid], sn);
    }
}

// ---------------- global kernel ----------------
__global__ void global_kernel(const float* __restrict__ u,
                              const float* __restrict__ w1, const float* __restrict__ b1,
                              const float* __restrict__ w2, const float* __restrict__ b2,
                              const float* __restrict__ w3, const float* __restrict__ b3,
                              const float* __restrict__ w4, const float* __restrict__ b4,
                              float* __restrict__ g_out) {
    __shared__ float sIn[272];
    __shared__ float sH[128];
    const int t = threadIdx.x;  // 128 threads
    if (t < 16) sIn[t] = u[t];
    sIn[16 + t]  = g_nsum[t];
    sIn[144 + t] = g_esum[t];
    __syncthreads();

    float a = b1[t];
#pragma unroll 4
    for (int k = 0; k < 272; k++) a = fmaf(sIn[k], w1[k * 128 + t], a);
    a = fmaxf(a, 0.f);
    __syncthreads(); sH[t] = a; __syncthreads();

    a = b2[t];
#pragma unroll 4
    for (int k = 0; k < 128; k++) a = fmaf(sH[k], w2[k * 128 + t], a);
    a = fmaxf(a, 0.f);
    __syncthreads(); sH[t] = a; __syncthreads();

    a = b3[t];
#pragma unroll 4
    for (int k = 0; k < 128; k++) a = fmaf(sH[k], w3[k * 128 + t], a);
    a = fmaxf(a, 0.f);
    __syncthreads(); sH[t] = a; __syncthreads();

    a = b4[t];
#pragma unroll 4
    for (int k = 0; k < 128; k++) a = fmaf(sH[k], w4[k * 128 + t], a);
    g_out[t] = a;
}

// ---------------- host launcher ----------------
extern "C" void kernel_launch(void* const* d_in, const int* in_sizes, int n_in,
                              void* d_out, int out_size) {
    const float* x  = (const float*)d_in[0];
    const float* ea = (const float*)d_in[1];
    const float* u  = (const float*)d_in[2];
    const void*  ei = d_in[3];

    const int N = in_sizes[0] / 16;
    const int E = in_sizes[1] / 16;

    float* out   = (float*)d_out;
    float* e_out = out;
    float* n_out = out + (long long)E * 128;
    float* g_out = out + (long long)E * 128 + (long long)N * 128;

    detect_kernel<<<1, 256>>>((const unsigned*)ei, E);
    zero_kernel<<<1024, 256>>>((long long)N * 128);
    prep_frag<<<dim3(8, 12), 256>>>((const float*)d_in[4],  (const float*)d_in[6],
                                    (const float*)d_in[8],  (const float*)d_in[10],
                                    (const float*)d_in[12], (const float*)d_in[14],
                                    (const float*)d_in[16], (const float*)d_in[18]);
    edge_kernel<<<(E + 63) / 64, 128>>>(
        x, ea, u, ei,
        (const float*)d_in[5], (const float*)d_in[7],
        (const float*)d_in[9], (const float*)d_in[11],
        e_out, N, E);
    node_kernel<<<(N + 63) / 64, 128>>>(
        x, u,
        (const float*)d_in[13], (const float*)d_in[15],
        (const float*)d_in[17], (const float*)d_in[19],
        n_out, N);
    global_kernel<<<1, 128>>>(
        u,
        (const float*)d_in[20], (const float*)d_in[21],
        (const float*)d_in[22], (const float*)d_in[23],
        (const float*)d_in[24], (const float*)d_in[25],
        (const float*)d_in[26], (const float*)d_in[27],
        g_out);
}